// round 1
// baseline (speedup 1.0000x reference)
#include <cuda_runtime.h>
#include <cuda_bf16.h>
#include <math.h>

#define NN 50000
#define EE 800000

// ---------------- scratch (static device globals; no runtime allocation) ----
static __device__ float g_A[(size_t)NN * 640];   // ping
static __device__ float g_B[(size_t)NN * 640];   // pong
static __device__ int   g_cnt[NN];
static __device__ int   g_cursor[NN];
static __device__ int   g_off[NN + 1];
static __device__ int   g_csr[EE];
static __device__ float g_dis[NN];

// ---------------- CSR build --------------------------------------------------
__global__ void k_zero() {
    int i = blockIdx.x * blockDim.x + threadIdx.x;
    if (i < NN) { g_cnt[i] = 0; g_cursor[i] = 0; }
}

__global__ void k_hist(const int* __restrict__ ei) {
    int e = blockIdx.x * blockDim.x + threadIdx.x;
    if (e < EE) {
        int d = ei[EE + e];           // edge_index[1][e] = dst
        atomicAdd(&g_cnt[d], 1);
    }
}

// single-block exclusive scan over g_cnt -> g_off, plus g_off[NN] = total
__global__ void k_scan() {
    __shared__ int sh[1024];
    const int CH = (NN + 1023) / 1024;   // 49
    int t = threadIdx.x;
    int beg = t * CH;
    int end = beg + CH; if (end > NN) end = NN;
    int s = 0;
    for (int i = beg; i < end; i++) s += g_cnt[i];
    sh[t] = s;
    __syncthreads();
    for (int off = 1; off < 1024; off <<= 1) {
        int v = (t >= off) ? sh[t - off] : 0;
        __syncthreads();
        sh[t] += v;
        __syncthreads();
    }
    int run = (t == 0) ? 0 : sh[t - 1];
    for (int i = beg; i < end; i++) { g_off[i] = run; run += g_cnt[i]; }
    if (t == 1023) g_off[NN] = sh[1023];
}

__global__ void k_dis() {
    int i = blockIdx.x * blockDim.x + threadIdx.x;
    if (i < NN) g_dis[i] = rsqrtf((float)(g_cnt[i] + 1));   // +1 self loop
}

__global__ void k_scatter(const int* __restrict__ ei) {
    int e = blockIdx.x * blockDim.x + threadIdx.x;
    if (e < EE) {
        int s = ei[e];                // src
        int d = ei[EE + e];           // dst
        int p = atomicAdd(&g_cursor[d], 1);
        g_csr[g_off[d] + p] = s;
    }
}

// ---------------- SGEMM: C[M,Nc] = A[M,K] @ W[K,Nc] -------------------------
#define BM 128
#define BN 128
#define BK 8
#define TM 8
#define TN 8

__global__ __launch_bounds__(256) void k_sgemm(
    const float* __restrict__ A, const float* __restrict__ W,
    float* __restrict__ C, int M, int K, int Nc)
{
    __shared__ float As[BK][BM];
    __shared__ float Bs[BK][BN];
    int tid = threadIdx.x;
    int tx = tid % 16, ty = tid / 16;
    int m0 = blockIdx.y * BM, n0 = blockIdx.x * BN;

    float acc[TM][TN];
    #pragma unroll
    for (int i = 0; i < TM; i++)
        #pragma unroll
        for (int j = 0; j < TN; j++) acc[i][j] = 0.f;

    int aRow = tid / 8;      // 0..31
    int aCol = tid % 8;      // 0..7
    int bRow = tid / 128;    // 0..1
    int bCol = tid % 128;

    for (int k0 = 0; k0 < K; k0 += BK) {
        #pragma unroll
        for (int i = 0; i < 4; i++) {
            int r  = aRow + i * 32;
            int gm = m0 + r, gk = k0 + aCol;
            As[aCol][r] = (gm < M && gk < K) ? A[(size_t)gm * K + gk] : 0.f;
        }
        #pragma unroll
        for (int i = 0; i < 4; i++) {
            int r  = bRow + i * 2;
            int gk = k0 + r, gn = n0 + bCol;
            Bs[r][bCol] = (gk < K && gn < Nc) ? W[(size_t)gk * Nc + gn] : 0.f;
        }
        __syncthreads();
        #pragma unroll
        for (int kk = 0; kk < BK; kk++) {
            float ra[TM], rb[TN];
            #pragma unroll
            for (int i = 0; i < TM; i++) ra[i] = As[kk][ty * TM + i];
            #pragma unroll
            for (int j = 0; j < TN; j++) rb[j] = Bs[kk][tx * TN + j];
            #pragma unroll
            for (int i = 0; i < TM; i++)
                #pragma unroll
                for (int j = 0; j < TN; j++)
                    acc[i][j] = fmaf(ra[i], rb[j], acc[i][j]);
        }
        __syncthreads();
    }

    #pragma unroll
    for (int i = 0; i < TM; i++) {
        int gm = m0 + ty * TM + i;
        if (gm >= M) continue;
        #pragma unroll
        for (int j = 0; j < TN; j++) {
            int gn = n0 + tx * TN + j;
            if (gn < Nc) C[(size_t)gm * Nc + gn] = acc[i][j];
        }
    }
}

// ---------------- aggregation: out[d] = sum_{s in N(d)} h[s]*dis[s]*dis[d]
//                  + h[d]*dis[d]^2, then +bias (+ReLU) ------------------------
template<int BT, int FPT>
__global__ __launch_bounds__(BT) void k_agg(
    const float* __restrict__ h, const float* __restrict__ bias,
    float* __restrict__ out, int F, int do_relu)
{
    int node = blockIdx.x;
    float dd = g_dis[node];
    int beg = g_off[node], end = g_off[node + 1];

    float acc[FPT];
    const float* hn = h + (size_t)node * F;
    #pragma unroll
    for (int i = 0; i < FPT; i++) {
        int f = threadIdx.x + i * BT;
        acc[i] = (f < F) ? hn[f] * dd * dd : 0.f;
    }
    for (int e = beg; e < end; e++) {
        int s = g_csr[e];
        float w = g_dis[s] * dd;
        const float* hs = h + (size_t)s * F;
        #pragma unroll
        for (int i = 0; i < FPT; i++) {
            int f = threadIdx.x + i * BT;
            if (f < F) acc[i] = fmaf(hs[f], w, acc[i]);
        }
    }
    float* on = out + (size_t)node * F;
    #pragma unroll
    for (int i = 0; i < FPT; i++) {
        int f = threadIdx.x + i * BT;
        if (f < F) {
            float v = acc[i] + bias[f];
            on[f] = do_relu ? fmaxf(v, 0.f) : v;
        }
    }
}

// ---------------- log_softmax over dim=10 ------------------------------------
__global__ void k_lsm(const float* __restrict__ in, float* __restrict__ out) {
    int i = blockIdx.x * blockDim.x + threadIdx.x;
    if (i >= NN) return;
    const float* r = in + (size_t)i * 10;
    float m = -1e30f;
    #pragma unroll
    for (int j = 0; j < 10; j++) m = fmaxf(m, r[j]);
    float s = 0.f;
    #pragma unroll
    for (int j = 0; j < 10; j++) s += __expf(r[j] - m);
    float l = __logf(s);
    float* o = out + (size_t)i * 10;
    #pragma unroll
    for (int j = 0; j < 10; j++) o[j] = r[j] - m - l;
}

// ---------------- driver -----------------------------------------------------
extern "C" void kernel_launch(void* const* d_in, const int* in_sizes, int n_in,
                              void* d_out, int out_size)
{
    const float* x  = (const float*)d_in[0];
    const int*   ei = (const int*)d_in[1];
    const float* W[6]; const float* b[6];
    for (int i = 0; i < 6; i++) {
        W[i] = (const float*)d_in[2 + 2 * i];
        b[i] = (const float*)d_in[3 + 2 * i];
    }

    float *A, *B;
    cudaGetSymbolAddress((void**)&A, g_A);
    cudaGetSymbolAddress((void**)&B, g_B);

    // CSR build
    k_zero   <<<(NN + 255) / 256, 256>>>();
    k_hist   <<<(EE + 255) / 256, 256>>>(ei);
    k_scan   <<<1, 1024>>>();
    k_dis    <<<(NN + 255) / 256, 256>>>();
    k_scatter<<<(EE + 255) / 256, 256>>>(ei);

    const int dims[7] = {767, 640, 512, 384, 256, 128, 10};
    const float* in = x;
    for (int l = 0; l < 6; l++) {
        int K = dims[l], F = dims[l + 1];
        dim3 grid((F + BN - 1) / BN, (NN + BM - 1) / BM);
        k_sgemm<<<grid, 256>>>(in, W[l], B, NN, K, F);
        int relu = (l < 5) ? 1 : 0;
        switch (F) {
            case 640: k_agg<256, 3><<<NN, 256>>>(B, b[l], A, F, relu); break;
            case 512: k_agg<256, 2><<<NN, 256>>>(B, b[l], A, F, relu); break;
            case 384: k_agg<128, 3><<<NN, 128>>>(B, b[l], A, F, relu); break;
            case 256: k_agg<256, 1><<<NN, 256>>>(B, b[l], A, F, relu); break;
            case 128: k_agg<128, 1><<<NN, 128>>>(B, b[l], A, F, relu); break;
            default:  k_agg< 32, 1><<<NN,  32>>>(B, b[l], A, F, relu); break;
        }
        in = A;
    }
    k_lsm<<<(NN + 255) / 256, 256>>>(A, (float*)d_out);
}

// round 3
// speedup vs baseline: 1.9597x; 1.9597x over previous
#include <cuda_runtime.h>
#include <cuda_bf16.h>
#include <cstdint>
#include <math.h>

#define NN 50000
#define EE 800000

// ---------------- scratch (static device globals) ---------------------------
static __device__ float g_A[(size_t)NN * 640];   // ping
static __device__ float g_B[(size_t)NN * 640];   // pong
static __device__ float g_X[(size_t)NN * 768];   // padded input
static __device__ float g_WT[640 * 768];         // transposed weight (padded K)
static __device__ int   g_cnt[NN];
static __device__ int   g_cursor[NN];
static __device__ int   g_off[NN + 1];
static __device__ int   g_csr[EE];
static __device__ float g_dis[NN];

// ---------------- CSR build --------------------------------------------------
__global__ void k_zero() {
    int i = blockIdx.x * blockDim.x + threadIdx.x;
    if (i < NN) { g_cnt[i] = 0; g_cursor[i] = 0; }
}
__global__ void k_hist(const int* __restrict__ ei) {
    int e = blockIdx.x * blockDim.x + threadIdx.x;
    if (e < EE) atomicAdd(&g_cnt[ei[EE + e]], 1);
}
__global__ void k_scan() {
    __shared__ int sh[1024];
    const int CH = (NN + 1023) / 1024;
    int t = threadIdx.x;
    int beg = t * CH, end = beg + CH; if (end > NN) end = NN;
    int s = 0;
    for (int i = beg; i < end; i++) s += g_cnt[i];
    sh[t] = s;
    __syncthreads();
    for (int off = 1; off < 1024; off <<= 1) {
        int v = (t >= off) ? sh[t - off] : 0;
        __syncthreads();
        sh[t] += v;
        __syncthreads();
    }
    int run = (t == 0) ? 0 : sh[t - 1];
    for (int i = beg; i < end; i++) { g_off[i] = run; run += g_cnt[i]; }
    if (t == 1023) g_off[NN] = sh[1023];
}
__global__ void k_dis() {
    int i = blockIdx.x * blockDim.x + threadIdx.x;
    if (i < NN) g_dis[i] = rsqrtf((float)(g_cnt[i] + 1));
}
__global__ void k_scatter(const int* __restrict__ ei) {
    int e = blockIdx.x * blockDim.x + threadIdx.x;
    if (e < EE) {
        int s = ei[e], d = ei[EE + e];
        int p = atomicAdd(&g_cursor[d], 1);
        g_csr[g_off[d] + p] = s;
    }
}

// ---------------- input pad: x[50000,767] -> g_X[50000,768] ------------------
__global__ void k_pad(const float* __restrict__ x) {
    int idx = blockIdx.x * blockDim.x + threadIdx.x;
    if (idx >= NN * 768) return;
    int m = idx / 768, k = idx - m * 768;
    g_X[idx] = (k < 767) ? x[(size_t)m * 767 + k] : 0.f;
}

// ---------------- weight transpose+pad: W[K,Nc] -> WT[Nc,KP] -----------------
__global__ void k_wT(const float* __restrict__ W, int K, int Nc, int KP) {
    int idx = blockIdx.x * blockDim.x + threadIdx.x;
    if (idx >= Nc * KP) return;
    int n = idx / KP, k = idx - n * KP;
    g_WT[idx] = (k < K) ? W[(size_t)k * Nc + n] : 0.f;
}

// ---------------- bf16x3 tensor-core GEMM ------------------------------------
// C[M,Nc] = A[M,KP] @ WT^T   (WT is [Nc,KP] row-major)
// Block tile 128x128x16; 8 warps, warp tile 64x32; mma.m16n8k16 bf16.
#define SSTR 24   // smem row stride in bf16 elems (16 data + 8 pad) -> conflict-free

__device__ __forceinline__ void mma_bf16(float* d, const uint32_t* a, const uint32_t* b) {
    asm volatile(
        "mma.sync.aligned.m16n8k16.row.col.f32.bf16.bf16.f32 "
        "{%0,%1,%2,%3}, {%4,%5,%6,%7}, {%8,%9}, {%0,%1,%2,%3};"
        : "+f"(d[0]), "+f"(d[1]), "+f"(d[2]), "+f"(d[3])
        : "r"(a[0]), "r"(a[1]), "r"(a[2]), "r"(a[3]), "r"(b[0]), "r"(b[1]));
}

__device__ __forceinline__ void split_store(
    __nv_bfloat16* hi, __nv_bfloat16* lo, int off, float4 v)
{
    __nv_bfloat16 hx = __float2bfloat16_rn(v.x);
    __nv_bfloat16 hy = __float2bfloat16_rn(v.y);
    __nv_bfloat16 hz = __float2bfloat16_rn(v.z);
    __nv_bfloat16 hw = __float2bfloat16_rn(v.w);
    __nv_bfloat162 h01; h01.x = hx; h01.y = hy;
    __nv_bfloat162 h23; h23.x = hz; h23.y = hw;
    *(__nv_bfloat162*)(hi + off)     = h01;
    *(__nv_bfloat162*)(hi + off + 2) = h23;
    __nv_bfloat162 l01, l23;
    l01.x = __float2bfloat16_rn(v.x - __bfloat162float(hx));
    l01.y = __float2bfloat16_rn(v.y - __bfloat162float(hy));
    l23.x = __float2bfloat16_rn(v.z - __bfloat162float(hz));
    l23.y = __float2bfloat16_rn(v.w - __bfloat162float(hw));
    *(__nv_bfloat162*)(lo + off)     = l01;
    *(__nv_bfloat162*)(lo + off + 2) = l23;
}

__global__ __launch_bounds__(256) void k_mm(
    const float* __restrict__ A, const float* __restrict__ WT,
    float* __restrict__ C, int M, int KP, int Nc)
{
    __shared__ __align__(16) __nv_bfloat16 sAh[128 * SSTR];
    __shared__ __align__(16) __nv_bfloat16 sAl[128 * SSTR];
    __shared__ __align__(16) __nv_bfloat16 sBh[128 * SSTR];
    __shared__ __align__(16) __nv_bfloat16 sBl[128 * SSTR];

    int tid = threadIdx.x;
    int lane = tid & 31, wid = tid >> 5;
    int wm = wid >> 2, wn = wid & 3;          // warp grid 2(M) x 4(N)
    int m0 = blockIdx.y * 128, n0 = blockIdx.x * 128;

    // global-load addressing: thread covers 2 float4 per tile
    int row0 = tid >> 2, q0 = tid & 3;        // j = tid
    int row1 = (tid + 256) >> 2, q1 = tid & 3;
    const int NC = KP >> 4;

    float4 ra0, ra1, rb0, rb1;
    auto load_tiles = [&](int c) {
        int k0 = c << 4;
        int gm0 = m0 + row0, gm1 = m0 + row1;
        ra0 = (gm0 < M) ? *(const float4*)(A + (size_t)gm0 * KP + k0 + q0 * 4)
                        : make_float4(0.f, 0.f, 0.f, 0.f);
        ra1 = (gm1 < M) ? *(const float4*)(A + (size_t)gm1 * KP + k0 + q1 * 4)
                        : make_float4(0.f, 0.f, 0.f, 0.f);
        rb0 = *(const float4*)(WT + (size_t)(n0 + row0) * KP + k0 + q0 * 4);
        rb1 = *(const float4*)(WT + (size_t)(n0 + row1) * KP + k0 + q1 * 4);
    };
    auto store_tiles = [&]() {
        split_store(sAh, sAl, row0 * SSTR + q0 * 4, ra0);
        split_store(sAh, sAl, row1 * SSTR + q1 * 4, ra1);
        split_store(sBh, sBl, row0 * SSTR + q0 * 4, rb0);
        split_store(sBh, sBl, row1 * SSTR + q1 * 4, rb1);
    };

    float acc[4][4][4];
    #pragma unroll
    for (int i = 0; i < 4; i++)
        #pragma unroll
        for (int j = 0; j < 4; j++)
            #pragma unroll
            for (int r = 0; r < 4; r++) acc[i][j][r] = 0.f;

    load_tiles(0);
    store_tiles();
    __syncthreads();

    const int lr = lane >> 2, lc = (lane & 3) * 2;

    for (int c = 0; c < NC; c++) {
        if (c + 1 < NC) load_tiles(c + 1);

        uint32_t ah[4][4], al[4][4], bh[4][2], bl[4][2];
        #pragma unroll
        for (int mf = 0; mf < 4; mf++) {
            int base = (wm * 64 + mf * 16 + lr) * SSTR + lc;
            ah[mf][0] = *(const uint32_t*)(sAh + base);
            ah[mf][1] = *(const uint32_t*)(sAh + base + 8 * SSTR);
            ah[mf][2] = *(const uint32_t*)(sAh + base + 8);
            ah[mf][3] = *(const uint32_t*)(sAh + base + 8 * SSTR + 8);
            al[mf][0] = *(const uint32_t*)(sAl + base);
            al[mf][1] = *(const uint32_t*)(sAl + base + 8 * SSTR);
            al[mf][2] = *(const uint32_t*)(sAl + base + 8);
            al[mf][3] = *(const uint32_t*)(sAl + base + 8 * SSTR + 8);
        }
        #pragma unroll
        for (int nf = 0; nf < 4; nf++) {
            int base = (wn * 32 + nf * 8 + lr) * SSTR + lc;
            bh[nf][0] = *(const uint32_t*)(sBh + base);
            bh[nf][1] = *(const uint32_t*)(sBh + base + 8);
            bl[nf][0] = *(const uint32_t*)(sBl + base);
            bl[nf][1] = *(const uint32_t*)(sBl + base + 8);
        }
        #pragma unroll
        for (int mf = 0; mf < 4; mf++)
            #pragma unroll
            for (int nf = 0; nf < 4; nf++) {
                mma_bf16(acc[mf][nf], ah[mf], bh[nf]);
                mma_bf16(acc[mf][nf], ah[mf], bl[nf]);
                mma_bf16(acc[mf][nf], al[mf], bh[nf]);
            }
        __syncthreads();
        if (c + 1 < NC) store_tiles();
        __syncthreads();
    }

    // epilogue
    #pragma unroll
    for (int mf = 0; mf < 4; mf++) {
        int r0 = m0 + wm * 64 + mf * 16 + lr;
        #pragma unroll
        for (int nf = 0; nf < 4; nf++) {
            int cc = n0 + wn * 32 + nf * 8 + lc;
            if (r0 < M)
                *(float2*)(C + (size_t)r0 * Nc + cc) =
                    make_float2(acc[mf][nf][0], acc[mf][nf][1]);
            if (r0 + 8 < M)
                *(float2*)(C + (size_t)(r0 + 8) * Nc + cc) =
                    make_float2(acc[mf][nf][2], acc[mf][nf][3]);
        }
    }
}

// ---------------- small GEMM for layer 6: K=128, N=10 (fp32) -----------------
__global__ __launch_bounds__(256) void k_small(
    const float* __restrict__ A, const float* __restrict__ W, float* __restrict__ C)
{
    __shared__ float Ws[128 * 10];
    for (int i = threadIdx.x; i < 1280; i += 256) Ws[i] = W[i];
    __syncthreads();
    int idx = blockIdx.x * 256 + threadIdx.x;
    if (idx >= NN * 10) return;
    int m = idx / 10, n = idx - m * 10;
    const float* ar = A + (size_t)m * 128;
    float acc = 0.f;
    #pragma unroll 8
    for (int k = 0; k < 128; k++) acc = fmaf(ar[k], Ws[k * 10 + n], acc);
    C[idx] = acc;
}

// ---------------- aggregation (float4, edge unroll x2) -----------------------
__global__ void k_aggv(const float4* __restrict__ h, const float4* __restrict__ bias,
                       float4* __restrict__ out, int relu)
{
    int node = blockIdx.x;
    int t = threadIdx.x;
    int F4 = blockDim.x;
    float dd = g_dis[node];
    float w0 = dd * dd;
    float4 a = h[(size_t)node * F4 + t];
    float4 acc = make_float4(a.x * w0, a.y * w0, a.z * w0, a.w * w0);
    int e = g_off[node], end = g_off[node + 1];
    for (; e + 1 < end; e += 2) {
        int s0 = g_csr[e], s1 = g_csr[e + 1];
        float u0 = g_dis[s0] * dd, u1 = g_dis[s1] * dd;
        float4 v0 = h[(size_t)s0 * F4 + t];
        float4 v1 = h[(size_t)s1 * F4 + t];
        acc.x = fmaf(v0.x, u0, fmaf(v1.x, u1, acc.x));
        acc.y = fmaf(v0.y, u0, fmaf(v1.y, u1, acc.y));
        acc.z = fmaf(v0.z, u0, fmaf(v1.z, u1, acc.z));
        acc.w = fmaf(v0.w, u0, fmaf(v1.w, u1, acc.w));
    }
    if (e < end) {
        int s0 = g_csr[e];
        float u0 = g_dis[s0] * dd;
        float4 v0 = h[(size_t)s0 * F4 + t];
        acc.x = fmaf(v0.x, u0, acc.x);
        acc.y = fmaf(v0.y, u0, acc.y);
        acc.z = fmaf(v0.z, u0, acc.z);
        acc.w = fmaf(v0.w, u0, acc.w);
    }
    float4 bb = bias[t];
    float4 r = make_float4(acc.x + bb.x, acc.y + bb.y, acc.z + bb.z, acc.w + bb.w);
    if (relu) {
        r.x = fmaxf(r.x, 0.f); r.y = fmaxf(r.y, 0.f);
        r.z = fmaxf(r.z, 0.f); r.w = fmaxf(r.w, 0.f);
    }
    out[(size_t)node * F4 + t] = r;
}

__global__ void k_agg10(const float* __restrict__ h, const float* __restrict__ bias,
                        float* __restrict__ out)
{
    int node = blockIdx.x;
    int f = threadIdx.x;
    if (f >= 10) return;
    float dd = g_dis[node];
    float acc = h[(size_t)node * 10 + f] * dd * dd;
    int e = g_off[node], end = g_off[node + 1];
    for (; e < end; e++) {
        int s = g_csr[e];
        acc = fmaf(h[(size_t)s * 10 + f], g_dis[s] * dd, acc);
    }
    out[(size_t)node * 10 + f] = acc + bias[f];
}

// ---------------- log_softmax over dim=10 ------------------------------------
__global__ void k_lsm(const float* __restrict__ in, float* __restrict__ out) {
    int i = blockIdx.x * blockDim.x + threadIdx.x;
    if (i >= NN) return;
    const float* r = in + (size_t)i * 10;
    float m = -1e30f;
    #pragma unroll
    for (int j = 0; j < 10; j++) m = fmaxf(m, r[j]);
    float s = 0.f;
    #pragma unroll
    for (int j = 0; j < 10; j++) s += __expf(r[j] - m);
    float l = __logf(s);
    float* o = out + (size_t)i * 10;
    #pragma unroll
    for (int j = 0; j < 10; j++) o[j] = r[j] - m - l;
}

// ---------------- driver -----------------------------------------------------
extern "C" void kernel_launch(void* const* d_in, const int* in_sizes, int n_in,
                              void* d_out, int out_size)
{
    const float* x  = (const float*)d_in[0];
    const int*   ei = (const int*)d_in[1];
    const float* W[6]; const float* b[6];
    for (int i = 0; i < 6; i++) {
        W[i] = (const float*)d_in[2 + 2 * i];
        b[i] = (const float*)d_in[3 + 2 * i];
    }

    float *A, *B, *X, *WT;
    cudaGetSymbolAddress((void**)&A,  g_A);
    cudaGetSymbolAddress((void**)&B,  g_B);
    cudaGetSymbolAddress((void**)&X,  g_X);
    cudaGetSymbolAddress((void**)&WT, g_WT);

    // CSR build + input pad
    k_zero   <<<(NN + 255) / 256, 256>>>();
    k_hist   <<<(EE + 255) / 256, 256>>>(ei);
    k_scan   <<<1, 1024>>>();
    k_dis    <<<(NN + 255) / 256, 256>>>();
    k_scatter<<<(EE + 255) / 256, 256>>>(ei);
    k_pad    <<<(NN * 768 + 255) / 256, 256>>>(x);

    const int dims[7] = {767, 640, 512, 384, 256, 128, 10};
    const int KPs[6]  = {768, 640, 512, 384, 256, 128};

    const float* in = X;
    for (int l = 0; l < 5; l++) {
        int K = dims[l], F = dims[l + 1], KP = KPs[l];
        k_wT<<<(F * KP + 255) / 256, 256>>>(W[l], K, F, KP);
        dim3 grid(F / 128, (NN + 127) / 128);
        k_mm<<<grid, 256>>>(in, WT, B, NN, KP, F);
        k_aggv<<<NN, F / 4>>>((const float4*)B, (const float4*)b[l], (float4*)A, 1);
        in = A;
    }
    // layer 6: K=128 -> N=10, fp32
    k_small<<<(NN * 10 + 255) / 256, 256>>>(A, W[5], B);
    k_agg10<<<NN, 32>>>(B, b[5], A);
    k_lsm<<<(NN + 255) / 256, 256>>>(A, (float*)d_out);
}

// round 4
// speedup vs baseline: 2.2512x; 1.1487x over previous
#include <cuda_runtime.h>
#include <cuda_bf16.h>
#include <cstdint>
#include <math.h>

#define NN 50000
#define EE 800000

// ---------------- scratch (static device globals) ---------------------------
static __device__ __nv_bfloat16 g_Ah[(size_t)NN * 768];  // activation hi
static __device__ __nv_bfloat16 g_Al[(size_t)NN * 768];  // activation lo
static __device__ float         g_C[(size_t)NN * 640];   // GEMM output
static __device__ __nv_bfloat16 g_Wh[640 * 768];
static __device__ __nv_bfloat16 g_Wl[640 * 768];
static __device__ float         g_S[(size_t)NN * 10];
static __device__ float         g_T[(size_t)NN * 10];
static __device__ int   g_cnt[NN];
static __device__ int   g_cursor[NN];
static __device__ int   g_off[NN + 1];
static __device__ int   g_csr[EE];
static __device__ float g_dis[NN];

__device__ __forceinline__ uint32_t sm_u32(const void* p) {
    uint32_t a;
    asm("{ .reg .u64 t; cvta.to.shared.u64 t, %1; cvt.u32.u64 %0, t; }"
        : "=r"(a) : "l"(p));
    return a;
}

// ---------------- CSR build --------------------------------------------------
__global__ void k_zero() {
    int i = blockIdx.x * blockDim.x + threadIdx.x;
    if (i < NN) { g_cnt[i] = 0; g_cursor[i] = 0; }
}
__global__ void k_hist(const int* __restrict__ ei) {
    int e = blockIdx.x * blockDim.x + threadIdx.x;
    if (e < EE) atomicAdd(&g_cnt[ei[EE + e]], 1);
}
// scan + dis fused
__global__ void k_scan() {
    __shared__ int sh[1024];
    const int CH = (NN + 1023) / 1024;
    int t = threadIdx.x;
    int beg = t * CH, end = beg + CH; if (end > NN) end = NN;
    int s = 0;
    for (int i = beg; i < end; i++) s += g_cnt[i];
    sh[t] = s;
    __syncthreads();
    for (int off = 1; off < 1024; off <<= 1) {
        int v = (t >= off) ? sh[t - off] : 0;
        __syncthreads();
        sh[t] += v;
        __syncthreads();
    }
    int run = (t == 0) ? 0 : sh[t - 1];
    for (int i = beg; i < end; i++) { g_off[i] = run; run += g_cnt[i]; }
    if (t == 1023) g_off[NN] = sh[1023];
    for (int i = beg; i < end; i++) g_dis[i] = rsqrtf((float)(g_cnt[i] + 1));
}
__global__ void k_scatter(const int* __restrict__ ei) {
    int e = blockIdx.x * blockDim.x + threadIdx.x;
    if (e < EE) {
        int s = ei[e], d = ei[EE + e];
        int p = atomicAdd(&g_cursor[d], 1);
        g_csr[g_off[d] + p] = s;
    }
}

// ---------------- input pad+split: x[NN,767] -> g_Ah/g_Al[NN,768] ------------
__global__ void k_pad(const float* __restrict__ x) {
    int idx = blockIdx.x * blockDim.x + threadIdx.x;     // over NN*192
    if (idx >= NN * 192) return;
    int m = idx / 192, j = idx - m * 192;
    int c0 = j * 4;
    float v[4];
    #pragma unroll
    for (int i = 0; i < 4; i++) {
        int c = c0 + i;
        v[i] = (c < 767) ? x[(size_t)m * 767 + c] : 0.f;
    }
    __nv_bfloat162 h0, h1, l0, l1;
    h0.x = __float2bfloat16_rn(v[0]); h0.y = __float2bfloat16_rn(v[1]);
    h1.x = __float2bfloat16_rn(v[2]); h1.y = __float2bfloat16_rn(v[3]);
    l0.x = __float2bfloat16_rn(v[0] - __bfloat162float(h0.x));
    l0.y = __float2bfloat16_rn(v[1] - __bfloat162float(h0.y));
    l1.x = __float2bfloat16_rn(v[2] - __bfloat162float(h1.x));
    l1.y = __float2bfloat16_rn(v[3] - __bfloat162float(h1.y));
    size_t o = (size_t)m * 768 + c0;
    *(__nv_bfloat162*)(g_Ah + o)     = h0;
    *(__nv_bfloat162*)(g_Ah + o + 2) = h1;
    *(__nv_bfloat162*)(g_Al + o)     = l0;
    *(__nv_bfloat162*)(g_Al + o + 2) = l1;
}

// ---------------- weight transpose+pad+split ---------------------------------
__global__ void k_wT(const float* __restrict__ W, int K, int Nc, int KP) {
    int idx = blockIdx.x * blockDim.x + threadIdx.x;
    if (idx >= Nc * KP) return;
    int n = idx / KP, k = idx - n * KP;
    float v = (k < K) ? W[(size_t)k * Nc + n] : 0.f;
    __nv_bfloat16 h = __float2bfloat16_rn(v);
    g_Wh[idx] = h;
    g_Wl[idx] = __float2bfloat16_rn(v - __bfloat162float(h));
}

// ---------------- bf16x3 tensor-core GEMM, cp.async 3-stage ------------------
// C[M,Nc] = (Ah+Al)[M,KP] @ (Wh+Wl)^T,  W arrays are [Nc,KP] row-major.
#define PIPE 3
#define TSTR 40                     // bf16 elems per smem row (32 data + 8 pad)
#define TILE_E (128 * TSTR)         // 5120 elems = 10240 B
#define STAGE_E (4 * TILE_E)
#define SMEM_MM (PIPE * STAGE_E * 2)  // 122880 B

__device__ __forceinline__ void cp16(uint32_t d, const void* s, int n) {
    asm volatile("cp.async.cg.shared.global [%0], [%1], 16, %2;\n"
                 :: "r"(d), "l"(s), "r"(n));
}
__device__ __forceinline__ void mma_bf16(float* d, const uint32_t* a, const uint32_t* b) {
    asm volatile(
        "mma.sync.aligned.m16n8k16.row.col.f32.bf16.bf16.f32 "
        "{%0,%1,%2,%3}, {%4,%5,%6,%7}, {%8,%9}, {%0,%1,%2,%3};"
        : "+f"(d[0]), "+f"(d[1]), "+f"(d[2]), "+f"(d[3])
        : "r"(a[0]), "r"(a[1]), "r"(a[2]), "r"(a[3]), "r"(b[0]), "r"(b[1]));
}

__global__ __launch_bounds__(256) void k_mm(
    const __nv_bfloat16* __restrict__ Ah, const __nv_bfloat16* __restrict__ Al,
    float* __restrict__ C, int M, int KP, int Nc)
{
    extern __shared__ __nv_bfloat16 smem[];
    uint32_t sb = sm_u32(smem);
    int tid = threadIdx.x, lane = tid & 31, wid = tid >> 5;
    int wm = wid >> 2, wn = wid & 3;
    int m0 = blockIdx.y * 128, n0 = blockIdx.x * 128;
    const int NC = KP >> 5;
    int lr = lane >> 2, lc = (lane & 3) * 2;

    // load coords: thread -> (row, two 16B chunks)
    int row = tid >> 1;
    int q0 = (tid & 1) * 2;                  // chunks q0, q0+1 (of 4 per row)
    int gm = m0 + row;
    int aok = (gm < M) ? 16 : 0;
    int gmc = (gm < M) ? gm : (M - 1);
    const __nv_bfloat16* pAh = Ah + (size_t)gmc * KP + q0 * 8;
    const __nv_bfloat16* pAl = Al + (size_t)gmc * KP + q0 * 8;
    const __nv_bfloat16* pBh = g_Wh + (size_t)(n0 + row) * KP + q0 * 8;
    const __nv_bfloat16* pBl = g_Wl + (size_t)(n0 + row) * KP + q0 * 8;
    uint32_t dro = (uint32_t)row * (TSTR * 2) + q0 * 16;

    auto issue = [&](int c) {
        int s = c % PIPE;
        int k0 = c << 5;
        uint32_t st = sb + (uint32_t)s * (STAGE_E * 2) + dro;
        cp16(st,                    pAh + k0,      aok);
        cp16(st + 16,               pAh + k0 + 8,  aok);
        cp16(st + TILE_E * 2,       pAl + k0,      aok);
        cp16(st + TILE_E * 2 + 16,  pAl + k0 + 8,  aok);
        cp16(st + TILE_E * 4,       pBh + k0,      16);
        cp16(st + TILE_E * 4 + 16,  pBh + k0 + 8,  16);
        cp16(st + TILE_E * 6,       pBl + k0,      16);
        cp16(st + TILE_E * 6 + 16,  pBl + k0 + 8,  16);
    };

    float acc[4][4][4];
    #pragma unroll
    for (int i = 0; i < 4; i++)
        #pragma unroll
        for (int j = 0; j < 4; j++)
            #pragma unroll
            for (int r = 0; r < 4; r++) acc[i][j][r] = 0.f;

    #pragma unroll
    for (int s = 0; s < PIPE - 1; s++) {
        issue(s);
        asm volatile("cp.async.commit_group;");
    }

    for (int c = 0; c < NC; c++) {
        asm volatile("cp.async.wait_group 1;");
        __syncthreads();
        int cn = c + PIPE - 1;
        if (cn < NC) issue(cn);
        asm volatile("cp.async.commit_group;");

        const __nv_bfloat16* st  = smem + (size_t)(c % PIPE) * STAGE_E;
        const __nv_bfloat16* tAh = st;
        const __nv_bfloat16* tAl = st + TILE_E;
        const __nv_bfloat16* tBh = st + 2 * TILE_E;
        const __nv_bfloat16* tBl = st + 3 * TILE_E;

        #pragma unroll
        for (int kh = 0; kh < 2; kh++) {
            int ko = kh * 16 + lc;
            uint32_t ah[4][4], al[4][4], bh[4][2], bl[4][2];
            #pragma unroll
            for (int mf = 0; mf < 4; mf++) {
                int base = (wm * 64 + mf * 16 + lr) * TSTR + ko;
                ah[mf][0] = *(const uint32_t*)(tAh + base);
                ah[mf][1] = *(const uint32_t*)(tAh + base + 8 * TSTR);
                ah[mf][2] = *(const uint32_t*)(tAh + base + 8);
                ah[mf][3] = *(const uint32_t*)(tAh + base + 8 * TSTR + 8);
                al[mf][0] = *(const uint32_t*)(tAl + base);
                al[mf][1] = *(const uint32_t*)(tAl + base + 8 * TSTR);
                al[mf][2] = *(const uint32_t*)(tAl + base + 8);
                al[mf][3] = *(const uint32_t*)(tAl + base + 8 * TSTR + 8);
            }
            #pragma unroll
            for (int nf = 0; nf < 4; nf++) {
                int base = (wn * 32 + nf * 8 + lr) * TSTR + ko;
                bh[nf][0] = *(const uint32_t*)(tBh + base);
                bh[nf][1] = *(const uint32_t*)(tBh + base + 8);
                bl[nf][0] = *(const uint32_t*)(tBl + base);
                bl[nf][1] = *(const uint32_t*)(tBl + base + 8);
            }
            #pragma unroll
            for (int mf = 0; mf < 4; mf++)
                #pragma unroll
                for (int nf = 0; nf < 4; nf++) {
                    mma_bf16(acc[mf][nf], ah[mf], bh[nf]);
                    mma_bf16(acc[mf][nf], ah[mf], bl[nf]);
                    mma_bf16(acc[mf][nf], al[mf], bh[nf]);
                }
        }
    }

    #pragma unroll
    for (int mf = 0; mf < 4; mf++) {
        int r0 = m0 + wm * 64 + mf * 16 + lr;
        #pragma unroll
        for (int nf = 0; nf < 4; nf++) {
            int cc = n0 + wn * 32 + nf * 8 + lc;
            if (r0 < M)
                *(float2*)(C + (size_t)r0 * Nc + cc) =
                    make_float2(acc[mf][nf][0], acc[mf][nf][1]);
            if (r0 + 8 < M)
                *(float2*)(C + (size_t)(r0 + 8) * Nc + cc) =
                    make_float2(acc[mf][nf][2], acc[mf][nf][3]);
        }
    }
}

// ---------------- small GEMM for layer 6: K=128, N=10 ------------------------
__global__ __launch_bounds__(256) void k_small(
    const __nv_bfloat16* __restrict__ Ah, const __nv_bfloat16* __restrict__ Al,
    const float* __restrict__ W, float* __restrict__ C)
{
    __shared__ float Ws[128 * 10];
    for (int i = threadIdx.x; i < 1280; i += 256) Ws[i] = W[i];
    __syncthreads();
    int idx = blockIdx.x * 256 + threadIdx.x;
    if (idx >= NN * 10) return;
    int m = idx / 10, n = idx - m * 10;
    const __nv_bfloat16* ah = Ah + (size_t)m * 128;
    const __nv_bfloat16* al = Al + (size_t)m * 128;
    float acc = 0.f;
    #pragma unroll 8
    for (int k = 0; k < 128; k++) {
        float a = __bfloat162float(ah[k]) + __bfloat162float(al[k]);
        acc = fmaf(a, Ws[k * 10 + n], acc);
    }
    C[idx] = acc;
}

// ---------------- aggregation -> bf16 hi/lo ----------------------------------
__global__ void k_aggv(const float4* __restrict__ h, const float4* __restrict__ bias,
                       __nv_bfloat162* __restrict__ oh, __nv_bfloat162* __restrict__ ol,
                       int relu)
{
    int node = blockIdx.x;
    int t = threadIdx.x;
    int F4 = blockDim.x;
    float dd = g_dis[node];
    float w0 = dd * dd;
    float4 a = h[(size_t)node * F4 + t];
    float4 acc = make_float4(a.x * w0, a.y * w0, a.z * w0, a.w * w0);
    int e = g_off[node], end = g_off[node + 1];
    for (; e + 1 < end; e += 2) {
        int s0 = g_csr[e], s1 = g_csr[e + 1];
        float u0 = g_dis[s0] * dd, u1 = g_dis[s1] * dd;
        float4 v0 = h[(size_t)s0 * F4 + t];
        float4 v1 = h[(size_t)s1 * F4 + t];
        acc.x = fmaf(v0.x, u0, fmaf(v1.x, u1, acc.x));
        acc.y = fmaf(v0.y, u0, fmaf(v1.y, u1, acc.y));
        acc.z = fmaf(v0.z, u0, fmaf(v1.z, u1, acc.z));
        acc.w = fmaf(v0.w, u0, fmaf(v1.w, u1, acc.w));
    }
    if (e < end) {
        int s0 = g_csr[e];
        float u0 = g_dis[s0] * dd;
        float4 v0 = h[(size_t)s0 * F4 + t];
        acc.x = fmaf(v0.x, u0, acc.x);
        acc.y = fmaf(v0.y, u0, acc.y);
        acc.z = fmaf(v0.z, u0, acc.z);
        acc.w = fmaf(v0.w, u0, acc.w);
    }
    float4 bb = bias[t];
    float4 r = make_float4(acc.x + bb.x, acc.y + bb.y, acc.z + bb.z, acc.w + bb.w);
    if (relu) {
        r.x = fmaxf(r.x, 0.f); r.y = fmaxf(r.y, 0.f);
        r.z = fmaxf(r.z, 0.f); r.w = fmaxf(r.w, 0.f);
    }
    __nv_bfloat162 h0, h1, l0, l1;
    h0.x = __float2bfloat16_rn(r.x); h0.y = __float2bfloat16_rn(r.y);
    h1.x = __float2bfloat16_rn(r.z); h1.y = __float2bfloat16_rn(r.w);
    l0.x = __float2bfloat16_rn(r.x - __bfloat162float(h0.x));
    l0.y = __float2bfloat16_rn(r.y - __bfloat162float(h0.y));
    l1.x = __float2bfloat16_rn(r.z - __bfloat162float(h1.x));
    l1.y = __float2bfloat16_rn(r.w - __bfloat162float(h1.y));
    size_t o = ((size_t)node * F4 + t) * 2;
    oh[o] = h0; oh[o + 1] = h1;
    ol[o] = l0; ol[o + 1] = l1;
}

__global__ void k_agg10(const float* __restrict__ h, const float* __restrict__ bias,
                        float* __restrict__ out)
{
    int node = blockIdx.x;
    int f = threadIdx.x;
    if (f >= 10) return;
    float dd = g_dis[node];
    float acc = h[(size_t)node * 10 + f] * dd * dd;
    int e = g_off[node], end = g_off[node + 1];
    for (; e < end; e++) {
        int s = g_csr[e];
        acc = fmaf(h[(size_t)s * 10 + f], g_dis[s] * dd, acc);
    }
    out[(size_t)node * 10 + f] = acc + bias[f];
}

// ---------------- log_softmax over dim=10 ------------------------------------
__global__ void k_lsm(const float* __restrict__ in, float* __restrict__ out) {
    int i = blockIdx.x * blockDim.x + threadIdx.x;
    if (i >= NN) return;
    const float* r = in + (size_t)i * 10;
    float m = -1e30f;
    #pragma unroll
    for (int j = 0; j < 10; j++) m = fmaxf(m, r[j]);
    float s = 0.f;
    #pragma unroll
    for (int j = 0; j < 10; j++) s += __expf(r[j] - m);
    float l = __logf(s);
    float* o = out + (size_t)i * 10;
    #pragma unroll
    for (int j = 0; j < 10; j++) o[j] = r[j] - m - l;
}

// ---------------- driver -----------------------------------------------------
extern "C" void kernel_launch(void* const* d_in, const int* in_sizes, int n_in,
                              void* d_out, int out_size)
{
    const float* x  = (const float*)d_in[0];
    const int*   ei = (const int*)d_in[1];
    const float* W[6]; const float* b[6];
    for (int i = 0; i < 6; i++) {
        W[i] = (const float*)d_in[2 + 2 * i];
        b[i] = (const float*)d_in[3 + 2 * i];
    }

    __nv_bfloat16 *Ah, *Al;
    float *C, *S, *T;
    cudaGetSymbolAddress((void**)&Ah, g_Ah);
    cudaGetSymbolAddress((void**)&Al, g_Al);
    cudaGetSymbolAddress((void**)&C,  g_C);
    cudaGetSymbolAddress((void**)&S,  g_S);
    cudaGetSymbolAddress((void**)&T,  g_T);

    cudaFuncSetAttribute(k_mm, cudaFuncAttributeMaxDynamicSharedMemorySize, SMEM_MM);

    const int dims[7] = {767, 640, 512, 384, 256, 128, 10};
    const int KPs[6]  = {768, 640, 512, 384, 256, 128};

    // order chosen so k_mm (layer 1) is the 4th launch for ncu capture
    k_pad <<<(NN * 192 + 255) / 256, 256>>>(x);                          // 1
    k_wT  <<<(640 * 768 + 255) / 256, 256>>>(W[0], 767, 640, 768);      // 2
    k_zero<<<(NN + 255) / 256, 256>>>();                                 // 3
    {
        dim3 grid(640 / 128, (NN + 127) / 128);
        k_mm<<<grid, 256, SMEM_MM>>>(Ah, Al, C, NN, 768, 640);           // 4
    }
    k_hist   <<<(EE + 255) / 256, 256>>>(ei);                            // 5
    k_scan   <<<1, 1024>>>();                                            // 6
    k_scatter<<<(EE + 255) / 256, 256>>>(ei);                            // 7
    k_aggv<<<NN, 640 / 4>>>((const float4*)C, (const float4*)b[0],
                            (__nv_bfloat162*)Ah, (__nv_bfloat162*)Al, 1);// 8

    for (int l = 1; l < 5; l++) {
        int K = dims[l], F = dims[l + 1], KP = KPs[l];
        k_wT<<<(F * KP + 255) / 256, 256>>>(W[l], K, F, KP);
        dim3 grid(F / 128, (NN + 127) / 128);
        k_mm<<<grid, 256, SMEM_MM>>>(Ah, Al, C, NN, KP, F);
        k_aggv<<<NN, F / 4>>>((const float4*)C, (const float4*)b[l],
                              (__nv_bfloat162*)Ah, (__nv_bfloat162*)Al, 1);
    }
    // layer 6: K=128 -> N=10, fp32
    k_small<<<(NN * 10 + 255) / 256, 256>>>(Ah, Al, W[5], S);
    k_agg10<<<NN, 32>>>(S, b[5], T);
    k_lsm<<<(NN + 255) / 256, 256>>>(T, (float*)d_out);
}

// round 5
// speedup vs baseline: 2.4899x; 1.1060x over previous
#include <cuda_runtime.h>
#include <cuda_bf16.h>
#include <cstdint>
#include <math.h>

#define NN 50000
#define EE 800000

// ---------------- scratch (static device globals) ---------------------------
static __device__ __nv_bfloat16 g_Ah[(size_t)NN * 768];  // activation hi
static __device__ __nv_bfloat16 g_Al[(size_t)NN * 768];  // activation lo
static __device__ float         g_C[(size_t)NN * 640];   // GEMM output
static __device__ __nv_bfloat16 g_Wh[640 * 768];
static __device__ __nv_bfloat16 g_Wl[640 * 768];
static __device__ float         g_S[(size_t)NN * 10];
static __device__ float         g_T[(size_t)NN * 10];
static __device__ int   g_cnt[NN];
static __device__ int   g_cursor[NN];
static __device__ int   g_off[NN + 1];
static __device__ int   g_csr[EE];
static __device__ float g_dis[NN];

__device__ __forceinline__ uint32_t sm_u32(const void* p) {
    uint32_t a;
    asm("{ .reg .u64 t; cvta.to.shared.u64 t, %1; cvt.u32.u64 %0, t; }"
        : "=r"(a) : "l"(p));
    return a;
}

// ---------------- CSR build --------------------------------------------------
__global__ void k_zero() {
    int i = blockIdx.x * blockDim.x + threadIdx.x;
    if (i < NN) { g_cnt[i] = 0; g_cursor[i] = 0; }
}
__global__ void k_hist(const int* __restrict__ ei) {
    int e = blockIdx.x * blockDim.x + threadIdx.x;
    if (e < EE) atomicAdd(&g_cnt[ei[EE + e]], 1);
}
__global__ void k_scan() {
    __shared__ int sh[1024];
    const int CH = (NN + 1023) / 1024;
    int t = threadIdx.x;
    int beg = t * CH, end = beg + CH; if (end > NN) end = NN;
    int s = 0;
    for (int i = beg; i < end; i++) s += g_cnt[i];
    sh[t] = s;
    __syncthreads();
    for (int off = 1; off < 1024; off <<= 1) {
        int v = (t >= off) ? sh[t - off] : 0;
        __syncthreads();
        sh[t] += v;
        __syncthreads();
    }
    int run = (t == 0) ? 0 : sh[t - 1];
    for (int i = beg; i < end; i++) { g_off[i] = run; run += g_cnt[i]; }
    if (t == 1023) g_off[NN] = sh[1023];
    for (int i = beg; i < end; i++) g_dis[i] = rsqrtf((float)(g_cnt[i] + 1));
}
__global__ void k_scatter(const int* __restrict__ ei) {
    int e = blockIdx.x * blockDim.x + threadIdx.x;
    if (e < EE) {
        int s = ei[e], d = ei[EE + e];
        int p = atomicAdd(&g_cursor[d], 1);
        g_csr[g_off[d] + p] = s;
    }
}

// ---------------- input pad+split --------------------------------------------
__global__ void k_pad(const float* __restrict__ x) {
    int idx = blockIdx.x * blockDim.x + threadIdx.x;     // over NN*192
    if (idx >= NN * 192) return;
    int m = idx / 192, j = idx - m * 192;
    int c0 = j * 4;
    float v[4];
    #pragma unroll
    for (int i = 0; i < 4; i++) {
        int c = c0 + i;
        v[i] = (c < 767) ? x[(size_t)m * 767 + c] : 0.f;
    }
    __nv_bfloat162 h0, h1, l0, l1;
    h0.x = __float2bfloat16_rn(v[0]); h0.y = __float2bfloat16_rn(v[1]);
    h1.x = __float2bfloat16_rn(v[2]); h1.y = __float2bfloat16_rn(v[3]);
    l0.x = __float2bfloat16_rn(v[0] - __bfloat162float(h0.x));
    l0.y = __float2bfloat16_rn(v[1] - __bfloat162float(h0.y));
    l1.x = __float2bfloat16_rn(v[2] - __bfloat162float(h1.x));
    l1.y = __float2bfloat16_rn(v[3] - __bfloat162float(h1.y));
    size_t o = (size_t)m * 768 + c0;
    *(__nv_bfloat162*)(g_Ah + o)     = h0;
    *(__nv_bfloat162*)(g_Ah + o + 2) = h1;
    *(__nv_bfloat162*)(g_Al + o)     = l0;
    *(__nv_bfloat162*)(g_Al + o + 2) = l1;
}

// ---------------- weight transpose+pad+split ---------------------------------
__global__ void k_wT(const float* __restrict__ W, int K, int Nc, int KP) {
    int idx = blockIdx.x * blockDim.x + threadIdx.x;
    if (idx >= Nc * KP) return;
    int n = idx / KP, k = idx - n * KP;
    float v = (k < K) ? W[(size_t)k * Nc + n] : 0.f;
    __nv_bfloat16 h = __float2bfloat16_rn(v);
    g_Wh[idx] = h;
    g_Wl[idx] = __float2bfloat16_rn(v - __bfloat162float(h));
}

// ---------------- bf16x3 tensor-core GEMM, cp.async double-buffer, ldmatrix --
#define PIPE 2
#define TSTR 40                       // bf16 elems per smem row (32 data + 8 pad)
#define TILE_E (128 * TSTR)           // 5120 elems
#define TILE_B (TILE_E * 2)           // 10240 bytes
#define STAGE_B (4 * TILE_B)          // 40960 bytes
#define SMEM_MM (PIPE * STAGE_B)      // 81920 bytes -> 2 CTAs/SM

__device__ __forceinline__ void cp16(uint32_t d, const void* s, int n) {
    asm volatile("cp.async.cg.shared.global [%0], [%1], 16, %2;\n"
                 :: "r"(d), "l"(s), "r"(n));
}
__device__ __forceinline__ void mma_bf16(float* d, const uint32_t* a, const uint32_t* b) {
    asm volatile(
        "mma.sync.aligned.m16n8k16.row.col.f32.bf16.bf16.f32 "
        "{%0,%1,%2,%3}, {%4,%5,%6,%7}, {%8,%9}, {%0,%1,%2,%3};"
        : "+f"(d[0]), "+f"(d[1]), "+f"(d[2]), "+f"(d[3])
        : "r"(a[0]), "r"(a[1]), "r"(a[2]), "r"(a[3]), "r"(b[0]), "r"(b[1]));
}
__device__ __forceinline__ void ldm_x4(uint32_t* r, uint32_t a) {
    asm volatile("ldmatrix.sync.aligned.m8n8.x4.shared.b16 {%0,%1,%2,%3}, [%4];"
                 : "=r"(r[0]), "=r"(r[1]), "=r"(r[2]), "=r"(r[3]) : "r"(a));
}
__device__ __forceinline__ void ldm_x2(uint32_t* r, uint32_t a) {
    asm volatile("ldmatrix.sync.aligned.m8n8.x2.shared.b16 {%0,%1}, [%2];"
                 : "=r"(r[0]), "=r"(r[1]) : "r"(a));
}

__global__ __launch_bounds__(256, 2) void k_mm(
    const __nv_bfloat16* __restrict__ Ah, const __nv_bfloat16* __restrict__ Al,
    float* __restrict__ C, int M, int KP, int Nc)
{
    extern __shared__ __nv_bfloat16 smem[];
    uint32_t sb = sm_u32(smem);
    int tid = threadIdx.x, lane = tid & 31, wid = tid >> 5;
    int wm = wid >> 2, wn = wid & 3;
    int m0 = blockIdx.y * 128, n0 = blockIdx.x * 128;
    const int NC = KP >> 5;
    int lr = lane >> 2, lc = (lane & 3) * 2;

    // ldmatrix per-lane offsets (bytes) within a tile
    int arow = lane & 15, asel = (lane >> 4) * 8;
    uint32_t offA = (uint32_t)((wm * 64 + arow) * TSTR + asel) * 2;
    int bl16 = lane & 15;
    uint32_t offB = (uint32_t)((wn * 32 + (bl16 & 7)) * TSTR + (bl16 >> 3) * 8) * 2;

    // cp.async coords
    int row = tid >> 1;
    int q0 = (tid & 1) * 2;
    int gm = m0 + row;
    int aok = (gm < M) ? 16 : 0;
    int gmc = (gm < M) ? gm : (M - 1);
    const __nv_bfloat16* pAh = Ah + (size_t)gmc * KP + q0 * 8;
    const __nv_bfloat16* pAl = Al + (size_t)gmc * KP + q0 * 8;
    const __nv_bfloat16* pBh = g_Wh + (size_t)(n0 + row) * KP + q0 * 8;
    const __nv_bfloat16* pBl = g_Wl + (size_t)(n0 + row) * KP + q0 * 8;
    uint32_t dro = (uint32_t)row * (TSTR * 2) + q0 * 16;

    auto issue = [&](int c) {
        int k0 = c << 5;
        uint32_t st = sb + (uint32_t)(c & 1) * STAGE_B + dro;
        cp16(st,                pAh + k0,     aok);
        cp16(st + 16,           pAh + k0 + 8, aok);
        cp16(st + TILE_B,       pAl + k0,     aok);
        cp16(st + TILE_B + 16,  pAl + k0 + 8, aok);
        cp16(st + 2*TILE_B,     pBh + k0,     16);
        cp16(st + 2*TILE_B + 16,pBh + k0 + 8, 16);
        cp16(st + 3*TILE_B,     pBl + k0,     16);
        cp16(st + 3*TILE_B + 16,pBl + k0 + 8, 16);
    };

    float acc[4][4][4];
    #pragma unroll
    for (int i = 0; i < 4; i++)
        #pragma unroll
        for (int j = 0; j < 4; j++)
            #pragma unroll
            for (int r = 0; r < 4; r++) acc[i][j][r] = 0.f;

    issue(0);
    asm volatile("cp.async.commit_group;");

    for (int c = 0; c < NC; c++) {
        asm volatile("cp.async.wait_group 0;");
        __syncthreads();
        if (c + 1 < NC) {
            issue(c + 1);
            asm volatile("cp.async.commit_group;");
        }
        uint32_t stb = sb + (uint32_t)(c & 1) * STAGE_B;
        uint32_t aAh = stb + offA, aAl = stb + TILE_B + offA;
        uint32_t aBh = stb + 2*TILE_B + offB, aBl = stb + 3*TILE_B + offB;

        #pragma unroll
        for (int kh = 0; kh < 2; kh++) {
            uint32_t ko = kh * 32;        // 16 bf16 = 32 bytes
            uint32_t ah[4][4], al[4][4], bh[4][2], bl[4][2];
            #pragma unroll
            for (int mf = 0; mf < 4; mf++) {
                uint32_t mo = (uint32_t)mf * (16 * TSTR * 2) + ko;
                ldm_x4(ah[mf], aAh + mo);
                ldm_x4(al[mf], aAl + mo);
            }
            #pragma unroll
            for (int nf = 0; nf < 4; nf++) {
                uint32_t no = (uint32_t)nf * (8 * TSTR * 2) + ko;
                ldm_x2(bh[nf], aBh + no);
                ldm_x2(bl[nf], aBl + no);
            }
            #pragma unroll
            for (int mf = 0; mf < 4; mf++)
                #pragma unroll
                for (int nf = 0; nf < 4; nf++) {
                    mma_bf16(acc[mf][nf], ah[mf], bh[nf]);
                    mma_bf16(acc[mf][nf], ah[mf], bl[nf]);
                    mma_bf16(acc[mf][nf], al[mf], bh[nf]);
                }
        }
        __syncthreads();
    }

    #pragma unroll
    for (int mf = 0; mf < 4; mf++) {
        int r0 = m0 + wm * 64 + mf * 16 + lr;
        #pragma unroll
        for (int nf = 0; nf < 4; nf++) {
            int cc = n0 + wn * 32 + nf * 8 + lc;
            if (r0 < M)
                *(float2*)(C + (size_t)r0 * Nc + cc) =
                    make_float2(acc[mf][nf][0], acc[mf][nf][1]);
            if (r0 + 8 < M)
                *(float2*)(C + (size_t)(r0 + 8) * Nc + cc) =
                    make_float2(acc[mf][nf][2], acc[mf][nf][3]);
        }
    }
}

// ---------------- small GEMM for layer 6: K=128, N=10 ------------------------
__global__ __launch_bounds__(256) void k_small(
    const __nv_bfloat16* __restrict__ Ah, const __nv_bfloat16* __restrict__ Al,
    const float* __restrict__ W, float* __restrict__ C)
{
    __shared__ float Ws[128 * 10];
    for (int i = threadIdx.x; i < 1280; i += 256) Ws[i] = W[i];
    __syncthreads();
    int idx = blockIdx.x * 256 + threadIdx.x;
    if (idx >= NN * 10) return;
    int m = idx / 10, n = idx - m * 10;
    const __nv_bfloat16* ah = Ah + (size_t)m * 128;
    const __nv_bfloat16* al = Al + (size_t)m * 128;
    float acc = 0.f;
    #pragma unroll 8
    for (int k = 0; k < 128; k++) {
        float a = __bfloat162float(ah[k]) + __bfloat162float(al[k]);
        acc = fmaf(a, Ws[k * 10 + n], acc);
    }
    C[idx] = acc;
}

// ---------------- aggregation -> bf16 hi/lo ----------------------------------
__global__ void k_aggv(const float4* __restrict__ h, const float4* __restrict__ bias,
                       __nv_bfloat162* __restrict__ oh, __nv_bfloat162* __restrict__ ol,
                       int relu)
{
    int node = blockIdx.x;
    int t = threadIdx.x;
    int F4 = blockDim.x;
    float dd = g_dis[node];
    float w0 = dd * dd;
    float4 a = h[(size_t)node * F4 + t];
    float4 acc = make_float4(a.x * w0, a.y * w0, a.z * w0, a.w * w0);
    int e = g_off[node], end = g_off[node + 1];
    for (; e + 1 < end; e += 2) {
        int s0 = g_csr[e], s1 = g_csr[e + 1];
        float u0 = g_dis[s0] * dd, u1 = g_dis[s1] * dd;
        float4 v0 = h[(size_t)s0 * F4 + t];
        float4 v1 = h[(size_t)s1 * F4 + t];
        acc.x = fmaf(v0.x, u0, fmaf(v1.x, u1, acc.x));
        acc.y = fmaf(v0.y, u0, fmaf(v1.y, u1, acc.y));
        acc.z = fmaf(v0.z, u0, fmaf(v1.z, u1, acc.z));
        acc.w = fmaf(v0.w, u0, fmaf(v1.w, u1, acc.w));
    }
    if (e < end) {
        int s0 = g_csr[e];
        float u0 = g_dis[s0] * dd;
        float4 v0 = h[(size_t)s0 * F4 + t];
        acc.x = fmaf(v0.x, u0, acc.x);
        acc.y = fmaf(v0.y, u0, acc.y);
        acc.z = fmaf(v0.z, u0, acc.z);
        acc.w = fmaf(v0.w, u0, acc.w);
    }
    float4 bb = bias[t];
    float4 r = make_float4(acc.x + bb.x, acc.y + bb.y, acc.z + bb.z, acc.w + bb.w);
    if (relu) {
        r.x = fmaxf(r.x, 0.f); r.y = fmaxf(r.y, 0.f);
        r.z = fmaxf(r.z, 0.f); r.w = fmaxf(r.w, 0.f);
    }
    __nv_bfloat162 h0, h1, l0, l1;
    h0.x = __float2bfloat16_rn(r.x); h0.y = __float2bfloat16_rn(r.y);
    h1.x = __float2bfloat16_rn(r.z); h1.y = __float2bfloat16_rn(r.w);
    l0.x = __float2bfloat16_rn(r.x - __bfloat162float(h0.x));
    l0.y = __float2bfloat16_rn(r.y - __bfloat162float(h0.y));
    l1.x = __float2bfloat16_rn(r.z - __bfloat162float(h1.x));
    l1.y = __float2bfloat16_rn(r.w - __bfloat162float(h1.y));
    size_t o = ((size_t)node * F4 + t) * 2;
    oh[o] = h0; oh[o + 1] = h1;
    ol[o] = l0; ol[o + 1] = l1;
}

__global__ void k_agg10(const float* __restrict__ h, const float* __restrict__ bias,
                        float* __restrict__ out)
{
    int node = blockIdx.x;
    int f = threadIdx.x;
    if (f >= 10) return;
    float dd = g_dis[node];
    float acc = h[(size_t)node * 10 + f] * dd * dd;
    int e = g_off[node], end = g_off[node + 1];
    for (; e < end; e++) {
        int s = g_csr[e];
        acc = fmaf(h[(size_t)s * 10 + f], g_dis[s] * dd, acc);
    }
    out[(size_t)node * 10 + f] = acc + bias[f];
}

// ---------------- log_softmax over dim=10 ------------------------------------
__global__ void k_lsm(const float* __restrict__ in, float* __restrict__ out) {
    int i = blockIdx.x * blockDim.x + threadIdx.x;
    if (i >= NN) return;
    const float* r = in + (size_t)i * 10;
    float m = -1e30f;
    #pragma unroll
    for (int j = 0; j < 10; j++) m = fmaxf(m, r[j]);
    float s = 0.f;
    #pragma unroll
    for (int j = 0; j < 10; j++) s += __expf(r[j] - m);
    float l = __logf(s);
    float* o = out + (size_t)i * 10;
    #pragma unroll
    for (int j = 0; j < 10; j++) o[j] = r[j] - m - l;
}

// ---------------- driver -----------------------------------------------------
extern "C" void kernel_launch(void* const* d_in, const int* in_sizes, int n_in,
                              void* d_out, int out_size)
{
    const float* x  = (const float*)d_in[0];
    const int*   ei = (const int*)d_in[1];
    const float* W[6]; const float* b[6];
    for (int i = 0; i < 6; i++) {
        W[i] = (const float*)d_in[2 + 2 * i];
        b[i] = (const float*)d_in[3 + 2 * i];
    }

    __nv_bfloat16 *Ah, *Al;
    float *C, *S, *T;
    cudaGetSymbolAddress((void**)&Ah, g_Ah);
    cudaGetSymbolAddress((void**)&Al, g_Al);
    cudaGetSymbolAddress((void**)&C,  g_C);
    cudaGetSymbolAddress((void**)&S,  g_S);
    cudaGetSymbolAddress((void**)&T,  g_T);

    cudaFuncSetAttribute(k_mm, cudaFuncAttributeMaxDynamicSharedMemorySize, SMEM_MM);

    const int dims[7] = {767, 640, 512, 384, 256, 128, 10};
    const int KPs[6]  = {768, 640, 512, 384, 256, 128};

    // order chosen so k_mm (layer 1) is the 4th launch for ncu capture
    k_pad <<<(NN * 192 + 255) / 256, 256>>>(x);                          // 1
    k_wT  <<<(640 * 768 + 255) / 256, 256>>>(W[0], 767, 640, 768);      // 2
    k_zero<<<(NN + 255) / 256, 256>>>();                                 // 3
    {
        dim3 grid(640 / 128, (NN + 127) / 128);
        k_mm<<<grid, 256, SMEM_MM>>>(Ah, Al, C, NN, 768, 640);           // 4
    }
    k_hist   <<<(EE + 255) / 256, 256>>>(ei);                            // 5
    k_scan   <<<1, 1024>>>();                                            // 6
    k_scatter<<<(EE + 255) / 256, 256>>>(ei);                            // 7
    k_aggv<<<NN, 640 / 4>>>((const float4*)C, (const float4*)b[0],
                            (__nv_bfloat162*)Ah, (__nv_bfloat162*)Al, 1);// 8

    for (int l = 1; l < 5; l++) {
        int K = dims[l], F = dims[l + 1], KP = KPs[l];
        k_wT<<<(F * KP + 255) / 256, 256>>>(W[l], K, F, KP);
        dim3 grid(F / 128, (NN + 127) / 128);
        k_mm<<<grid, 256, SMEM_MM>>>(Ah, Al, C, NN, KP, F);
        k_aggv<<<NN, F / 4>>>((const float4*)C, (const float4*)b[l],
                              (__nv_bfloat162*)Ah, (__nv_bfloat162*)Al, 1);
    }
    // layer 6: K=128 -> N=10, fp32
    k_small<<<(NN * 10 + 255) / 256, 256>>>(Ah, Al, W[5], S);
    k_agg10<<<NN, 32>>>(S, b[5], T);
    k_lsm<<<(NN + 255) / 256, 256>>>(T, (float*)d_out);
}

// round 6
// speedup vs baseline: 2.5858x; 1.0385x over previous
#include <cuda_runtime.h>
#include <cuda_bf16.h>
#include <cstdint>
#include <math.h>

#define NN 50000
#define EE 800000

// ---------------- scratch (static device globals) ---------------------------
static __device__ __nv_bfloat16 g_Ah[(size_t)NN * 768];  // activation hi
static __device__ __nv_bfloat16 g_Al[(size_t)NN * 768];  // activation lo
static __device__ float         g_C[(size_t)NN * 640];   // GEMM output
static __device__ __nv_bfloat16 g_Wh[640 * 768];
static __device__ __nv_bfloat16 g_Wl[640 * 768];
static __device__ float         g_S[(size_t)NN * 10];
static __device__ float         g_T[(size_t)NN * 10];
static __device__ int   g_cnt[NN];
static __device__ int   g_cursor[NN];
static __device__ int   g_off[NN + 1];
static __device__ int   g_csr[EE];
static __device__ float g_dis[NN];

__device__ __forceinline__ uint32_t sm_u32(const void* p) {
    uint32_t a;
    asm("{ .reg .u64 t; cvta.to.shared.u64 t, %1; cvt.u32.u64 %0, t; }"
        : "=r"(a) : "l"(p));
    return a;
}

// ---------------- CSR build --------------------------------------------------
__global__ void k_zero() {
    int i = blockIdx.x * blockDim.x + threadIdx.x;
    if (i < NN) { g_cnt[i] = 0; g_cursor[i] = 0; }
}
__global__ void k_hist(const int* __restrict__ ei) {
    int e = blockIdx.x * blockDim.x + threadIdx.x;
    if (e < EE) atomicAdd(&g_cnt[ei[EE + e]], 1);
}
__global__ void k_scan() {
    __shared__ int sh[1024];
    const int CH = (NN + 1023) / 1024;
    int t = threadIdx.x;
    int beg = t * CH, end = beg + CH; if (end > NN) end = NN;
    int s = 0;
    for (int i = beg; i < end; i++) s += g_cnt[i];
    sh[t] = s;
    __syncthreads();
    for (int off = 1; off < 1024; off <<= 1) {
        int v = (t >= off) ? sh[t - off] : 0;
        __syncthreads();
        sh[t] += v;
        __syncthreads();
    }
    int run = (t == 0) ? 0 : sh[t - 1];
    for (int i = beg; i < end; i++) { g_off[i] = run; run += g_cnt[i]; }
    if (t == 1023) g_off[NN] = sh[1023];
    for (int i = beg; i < end; i++) g_dis[i] = rsqrtf((float)(g_cnt[i] + 1));
}
__global__ void k_scatter(const int* __restrict__ ei) {
    int e = blockIdx.x * blockDim.x + threadIdx.x;
    if (e < EE) {
        int s = ei[e], d = ei[EE + e];
        int p = atomicAdd(&g_cursor[d], 1);
        g_csr[g_off[d] + p] = s;
    }
}

// ---------------- input pad+split --------------------------------------------
__global__ void k_pad(const float* __restrict__ x) {
    int idx = blockIdx.x * blockDim.x + threadIdx.x;     // over NN*192
    if (idx >= NN * 192) return;
    int m = idx / 192, j = idx - m * 192;
    int c0 = j * 4;
    float v[4];
    #pragma unroll
    for (int i = 0; i < 4; i++) {
        int c = c0 + i;
        v[i] = (c < 767) ? x[(size_t)m * 767 + c] : 0.f;
    }
    __nv_bfloat162 h0, h1, l0, l1;
    h0.x = __float2bfloat16_rn(v[0]); h0.y = __float2bfloat16_rn(v[1]);
    h1.x = __float2bfloat16_rn(v[2]); h1.y = __float2bfloat16_rn(v[3]);
    l0.x = __float2bfloat16_rn(v[0] - __bfloat162float(h0.x));
    l0.y = __float2bfloat16_rn(v[1] - __bfloat162float(h0.y));
    l1.x = __float2bfloat16_rn(v[2] - __bfloat162float(h1.x));
    l1.y = __float2bfloat16_rn(v[3] - __bfloat162float(h1.y));
    size_t o = (size_t)m * 768 + c0;
    *(__nv_bfloat162*)(g_Ah + o)     = h0;
    *(__nv_bfloat162*)(g_Ah + o + 2) = h1;
    *(__nv_bfloat162*)(g_Al + o)     = l0;
    *(__nv_bfloat162*)(g_Al + o + 2) = l1;
}

// ---------------- weight transpose+pad+split ---------------------------------
__global__ void k_wT(const float* __restrict__ W, int K, int Nc, int KP) {
    int idx = blockIdx.x * blockDim.x + threadIdx.x;
    if (idx >= Nc * KP) return;
    int n = idx / KP, k = idx - n * KP;
    float v = (k < K) ? W[(size_t)k * Nc + n] : 0.f;
    __nv_bfloat16 h = __float2bfloat16_rn(v);
    g_Wh[idx] = h;
    g_Wl[idx] = __float2bfloat16_rn(v - __bfloat162float(h));
}

// ---------------- bf16x3 tensor-core GEMM, 3-stage cp.async, XOR swizzle -----
// tile: 128 rows x 32 bf16 (64B row), chunk = 16B, swizzle chunk ^= (row>>1)&3
#define PIPE 3
#define TILE_B 8192                  // 128 * 64 bytes
#define STAGE_B (4 * TILE_B)         // 32768
#define SMEM_MM (PIPE * STAGE_B)     // 98304 -> 2 CTAs/SM

__device__ __forceinline__ void cp16(uint32_t d, const void* s, int n) {
    asm volatile("cp.async.cg.shared.global [%0], [%1], 16, %2;\n"
                 :: "r"(d), "l"(s), "r"(n));
}
__device__ __forceinline__ void mma_bf16(float* d, const uint32_t* a, const uint32_t* b) {
    asm volatile(
        "mma.sync.aligned.m16n8k16.row.col.f32.bf16.bf16.f32 "
        "{%0,%1,%2,%3}, {%4,%5,%6,%7}, {%8,%9}, {%0,%1,%2,%3};"
        : "+f"(d[0]), "+f"(d[1]), "+f"(d[2]), "+f"(d[3])
        : "r"(a[0]), "r"(a[1]), "r"(a[2]), "r"(a[3]), "r"(b[0]), "r"(b[1]));
}
__device__ __forceinline__ void ldm_x4(uint32_t* r, uint32_t a) {
    asm volatile("ldmatrix.sync.aligned.m8n8.x4.shared.b16 {%0,%1,%2,%3}, [%4];"
                 : "=r"(r[0]), "=r"(r[1]), "=r"(r[2]), "=r"(r[3]) : "r"(a));
}
__device__ __forceinline__ void ldm_x2(uint32_t* r, uint32_t a) {
    asm volatile("ldmatrix.sync.aligned.m8n8.x2.shared.b16 {%0,%1}, [%2];"
                 : "=r"(r[0]), "=r"(r[1]) : "r"(a));
}
__device__ __forceinline__ uint32_t swzo(int row, int chunk) {
    return (uint32_t)(row * 64 + ((chunk ^ ((row >> 1) & 3)) * 16));
}

__global__ __launch_bounds__(256, 2) void k_mm(
    const __nv_bfloat16* __restrict__ Ah, const __nv_bfloat16* __restrict__ Al,
    float* __restrict__ C, int M, int KP, int Nc)
{
    extern __shared__ __nv_bfloat16 smem[];
    uint32_t sb = sm_u32(smem);
    int tid = threadIdx.x, lane = tid & 31, wid = tid >> 5;
    int wm = wid >> 2, wn = wid & 3;
    int m0 = blockIdx.y * 128, n0 = blockIdx.x * 128;
    const int NC = KP >> 5;
    int lr = lane >> 2, lc = (lane & 3) * 2;

    // ldmatrix per-lane swizzled offsets within a tile, per k-half
    int rbA = wm * 64 + (lane & 15);
    int csA = lane >> 4;
    uint32_t offA0 = swzo(rbA, csA);        // kh=0: chunks 0/1
    uint32_t offA1 = swzo(rbA, 2 + csA);    // kh=1: chunks 2/3
    int rbB = wn * 32 + (lane & 7);
    int csB = (lane >> 3) & 1;
    uint32_t offB0 = swzo(rbB, csB);
    uint32_t offB1 = swzo(rbB, 2 + csB);

    // cp.async coords
    int row = tid >> 1;
    int q0 = (tid & 1) * 2;
    int gm = m0 + row;
    int aok = (gm < M) ? 16 : 0;
    int gmc = (gm < M) ? gm : (M - 1);
    const __nv_bfloat16* pAh = Ah + (size_t)gmc * KP + q0 * 8;
    const __nv_bfloat16* pAl = Al + (size_t)gmc * KP + q0 * 8;
    const __nv_bfloat16* pBh = g_Wh + (size_t)(n0 + row) * KP + q0 * 8;
    const __nv_bfloat16* pBl = g_Wl + (size_t)(n0 + row) * KP + q0 * 8;
    uint32_t dro0 = swzo(row, q0);
    uint32_t dro1 = swzo(row, q0 + 1);

    auto issue = [&](int c) {
        int k0 = c << 5;
        uint32_t st = sb + (uint32_t)(c % PIPE) * STAGE_B;
        cp16(st + dro0,              pAh + k0,     aok);
        cp16(st + dro1,              pAh + k0 + 8, aok);
        cp16(st + TILE_B + dro0,     pAl + k0,     aok);
        cp16(st + TILE_B + dro1,     pAl + k0 + 8, aok);
        cp16(st + 2*TILE_B + dro0,   pBh + k0,     16);
        cp16(st + 2*TILE_B + dro1,   pBh + k0 + 8, 16);
        cp16(st + 3*TILE_B + dro0,   pBl + k0,     16);
        cp16(st + 3*TILE_B + dro1,   pBl + k0 + 8, 16);
    };

    float acc[4][4][4];
    #pragma unroll
    for (int i = 0; i < 4; i++)
        #pragma unroll
        for (int j = 0; j < 4; j++)
            #pragma unroll
            for (int r = 0; r < 4; r++) acc[i][j][r] = 0.f;

    issue(0);
    asm volatile("cp.async.commit_group;");
    issue(1);
    asm volatile("cp.async.commit_group;");

    for (int c = 0; c < NC; c++) {
        asm volatile("cp.async.wait_group 1;");
        __syncthreads();
        if (c + 2 < NC) issue(c + 2);
        asm volatile("cp.async.commit_group;");   // always commit (FIFO bookkeeping)

        uint32_t stb = sb + (uint32_t)(c % PIPE) * STAGE_B;

        #pragma unroll
        for (int kh = 0; kh < 2; kh++) {
            uint32_t oA = kh ? offA1 : offA0;
            uint32_t oB = kh ? offB1 : offB0;
            uint32_t ah[4][4], al[4][4], bh[4][2], bl[4][2];
            #pragma unroll
            for (int mf = 0; mf < 4; mf++) {
                uint32_t mo = (uint32_t)mf * 1024;   // 16 rows * 64B
                ldm_x4(ah[mf], stb + oA + mo);
                ldm_x4(al[mf], stb + TILE_B + oA + mo);
            }
            #pragma unroll
            for (int nf = 0; nf < 4; nf++) {
                uint32_t no = (uint32_t)nf * 512;    // 8 rows * 64B
                ldm_x2(bh[nf], stb + 2*TILE_B + oB + no);
                ldm_x2(bl[nf], stb + 3*TILE_B + oB + no);
            }
            #pragma unroll
            for (int mf = 0; mf < 4; mf++)
                #pragma unroll
                for (int nf = 0; nf < 4; nf++) {
                    mma_bf16(acc[mf][nf], ah[mf], bh[nf]);
                    mma_bf16(acc[mf][nf], ah[mf], bl[nf]);
                    mma_bf16(acc[mf][nf], al[mf], bh[nf]);
                }
        }
    }

    #pragma unroll
    for (int mf = 0; mf < 4; mf++) {
        int r0 = m0 + wm * 64 + mf * 16 + lr;
        #pragma unroll
        for (int nf = 0; nf < 4; nf++) {
            int cc = n0 + wn * 32 + nf * 8 + lc;
            if (r0 < M)
                *(float2*)(C + (size_t)r0 * Nc + cc) =
                    make_float2(acc[mf][nf][0], acc[mf][nf][1]);
            if (r0 + 8 < M)
                *(float2*)(C + (size_t)(r0 + 8) * Nc + cc) =
                    make_float2(acc[mf][nf][2], acc[mf][nf][3]);
        }
    }
}

// ---------------- small GEMM for layer 6: K=128, N=10 ------------------------
__global__ __launch_bounds__(256) void k_small(
    const __nv_bfloat16* __restrict__ Ah, const __nv_bfloat16* __restrict__ Al,
    const float* __restrict__ W, float* __restrict__ C)
{
    __shared__ float Ws[128 * 10];
    for (int i = threadIdx.x; i < 1280; i += 256) Ws[i] = W[i];
    __syncthreads();
    int idx = blockIdx.x * 256 + threadIdx.x;
    if (idx >= NN * 10) return;
    int m = idx / 10, n = idx - m * 10;
    const __nv_bfloat16* ah = Ah + (size_t)m * 128;
    const __nv_bfloat16* al = Al + (size_t)m * 128;
    float acc = 0.f;
    #pragma unroll 8
    for (int k = 0; k < 128; k++) {
        float a = __bfloat162float(ah[k]) + __bfloat162float(al[k]);
        acc = fmaf(a, Ws[k * 10 + n], acc);
    }
    C[idx] = acc;
}

// ---------------- aggregation -> bf16 hi/lo ----------------------------------
__global__ void k_aggv(const float4* __restrict__ h, const float4* __restrict__ bias,
                       __nv_bfloat162* __restrict__ oh, __nv_bfloat162* __restrict__ ol,
                       int relu)
{
    int node = blockIdx.x;
    int t = threadIdx.x;
    int F4 = blockDim.x;
    float dd = g_dis[node];
    float w0 = dd * dd;
    float4 a = h[(size_t)node * F4 + t];
    float4 acc = make_float4(a.x * w0, a.y * w0, a.z * w0, a.w * w0);
    int e = g_off[node], end = g_off[node + 1];
    for (; e + 1 < end; e += 2) {
        int s0 = g_csr[e], s1 = g_csr[e + 1];
        float u0 = g_dis[s0] * dd, u1 = g_dis[s1] * dd;
        float4 v0 = h[(size_t)s0 * F4 + t];
        float4 v1 = h[(size_t)s1 * F4 + t];
        acc.x = fmaf(v0.x, u0, fmaf(v1.x, u1, acc.x));
        acc.y = fmaf(v0.y, u0, fmaf(v1.y, u1, acc.y));
        acc.z = fmaf(v0.z, u0, fmaf(v1.z, u1, acc.z));
        acc.w = fmaf(v0.w, u0, fmaf(v1.w, u1, acc.w));
    }
    if (e < end) {
        int s0 = g_csr[e];
        float u0 = g_dis[s0] * dd;
        float4 v0 = h[(size_t)s0 * F4 + t];
        acc.x = fmaf(v0.x, u0, acc.x);
        acc.y = fmaf(v0.y, u0, acc.y);
        acc.z = fmaf(v0.z, u0, acc.z);
        acc.w = fmaf(v0.w, u0, acc.w);
    }
    float4 bb = bias[t];
    float4 r = make_float4(acc.x + bb.x, acc.y + bb.y, acc.z + bb.z, acc.w + bb.w);
    if (relu) {
        r.x = fmaxf(r.x, 0.f); r.y = fmaxf(r.y, 0.f);
        r.z = fmaxf(r.z, 0.f); r.w = fmaxf(r.w, 0.f);
    }
    __nv_bfloat162 h0, h1, l0, l1;
    h0.x = __float2bfloat16_rn(r.x); h0.y = __float2bfloat16_rn(r.y);
    h1.x = __float2bfloat16_rn(r.z); h1.y = __float2bfloat16_rn(r.w);
    l0.x = __float2bfloat16_rn(r.x - __bfloat162float(h0.x));
    l0.y = __float2bfloat16_rn(r.y - __bfloat162float(h0.y));
    l1.x = __float2bfloat16_rn(r.z - __bfloat162float(h1.x));
    l1.y = __float2bfloat16_rn(r.w - __bfloat162float(h1.y));
    size_t o = ((size_t)node * F4 + t) * 2;
    oh[o] = h0; oh[o + 1] = h1;
    ol[o] = l0; ol[o + 1] = l1;
}

__global__ void k_agg10(const float* __restrict__ h, const float* __restrict__ bias,
                        float* __restrict__ out)
{
    int node = blockIdx.x;
    int f = threadIdx.x;
    if (f >= 10) return;
    float dd = g_dis[node];
    float acc = h[(size_t)node * 10 + f] * dd * dd;
    int e = g_off[node], end = g_off[node + 1];
    for (; e < end; e++) {
        int s = g_csr[e];
        acc = fmaf(h[(size_t)s * 10 + f], g_dis[s] * dd, acc);
    }
    out[(size_t)node * 10 + f] = acc + bias[f];
}

// ---------------- log_softmax over dim=10 ------------------------------------
__global__ void k_lsm(const float* __restrict__ in, float* __restrict__ out) {
    int i = blockIdx.x * blockDim.x + threadIdx.x;
    if (i >= NN) return;
    const float* r = in + (size_t)i * 10;
    float m = -1e30f;
    #pragma unroll
    for (int j = 0; j < 10; j++) m = fmaxf(m, r[j]);
    float s = 0.f;
    #pragma unroll
    for (int j = 0; j < 10; j++) s += __expf(r[j] - m);
    float l = __logf(s);
    float* o = out + (size_t)i * 10;
    #pragma unroll
    for (int j = 0; j < 10; j++) o[j] = r[j] - m - l;
}

// ---------------- driver -----------------------------------------------------
extern "C" void kernel_launch(void* const* d_in, const int* in_sizes, int n_in,
                              void* d_out, int out_size)
{
    const float* x  = (const float*)d_in[0];
    const int*   ei = (const int*)d_in[1];
    const float* W[6]; const float* b[6];
    for (int i = 0; i < 6; i++) {
        W[i] = (const float*)d_in[2 + 2 * i];
        b[i] = (const float*)d_in[3 + 2 * i];
    }

    __nv_bfloat16 *Ah, *Al;
    float *C, *S, *T;
    cudaGetSymbolAddress((void**)&Ah, g_Ah);
    cudaGetSymbolAddress((void**)&Al, g_Al);
    cudaGetSymbolAddress((void**)&C,  g_C);
    cudaGetSymbolAddress((void**)&S,  g_S);
    cudaGetSymbolAddress((void**)&T,  g_T);

    cudaFuncSetAttribute(k_mm, cudaFuncAttributeMaxDynamicSharedMemorySize, SMEM_MM);

    const int dims[7] = {767, 640, 512, 384, 256, 128, 10};
    const int KPs[6]  = {768, 640, 512, 384, 256, 128};

    // order chosen so k_mm (layer 1) is the 4th launch for ncu capture
    k_pad <<<(NN * 192 + 255) / 256, 256>>>(x);                          // 1
    k_wT  <<<(640 * 768 + 255) / 256, 256>>>(W[0], 767, 640, 768);      // 2
    k_zero<<<(NN + 255) / 256, 256>>>();                                 // 3
    {
        dim3 grid(640 / 128, (NN + 127) / 128);
        k_mm<<<grid, 256, SMEM_MM>>>(Ah, Al, C, NN, 768, 640);           // 4
    }
    k_hist   <<<(EE + 255) / 256, 256>>>(ei);                            // 5
    k_scan   <<<1, 1024>>>();                                            // 6
    k_scatter<<<(EE + 255) / 256, 256>>>(ei);                            // 7
    k_aggv<<<NN, 640 / 4>>>((const float4*)C, (const float4*)b[0],
                            (__nv_bfloat162*)Ah, (__nv_bfloat162*)Al, 1);// 8

    for (int l = 1; l < 5; l++) {
        int K = dims[l], F = dims[l + 1], KP = KPs[l];
        k_wT<<<(F * KP + 255) / 256, 256>>>(W[l], K, F, KP);
        dim3 grid(F / 128, (NN + 127) / 128);
        k_mm<<<grid, 256, SMEM_MM>>>(Ah, Al, C, NN, KP, F);
        k_aggv<<<NN, F / 4>>>((const float4*)C, (const float4*)b[l],
                              (__nv_bfloat162*)Ah, (__nv_bfloat162*)Al, 1);
    }
    // layer 6: K=128 -> N=10, fp32
    k_small<<<(NN * 10 + 255) / 256, 256>>>(Ah, Al, W[5], S);
    k_agg10<<<NN, 32>>>(S, b[5], T);
    k_lsm<<<(NN + 255) / 256, 256>>>(T, (float*)d_out);
}

// round 7
// speedup vs baseline: 2.6019x; 1.0062x over previous
#include <cuda_runtime.h>
#include <cuda_bf16.h>
#include <cstdint>
#include <math.h>

#define NN 50000
#define EE 800000

// ---------------- scratch (static device globals) ---------------------------
static __device__ __nv_bfloat16 g_Ah[(size_t)NN * 768];  // activation hi
static __device__ __nv_bfloat16 g_Al[(size_t)NN * 768];  // activation lo
static __device__ float         g_C[(size_t)NN * 640];   // GEMM output
static __device__ __nv_bfloat16 g_Wh[640 * 768];
static __device__ __nv_bfloat16 g_Wl[640 * 768];
static __device__ float         g_S[(size_t)NN * 10];
static __device__ float         g_T[(size_t)NN * 10];
static __device__ int   g_cnt[NN];
static __device__ int   g_cursor[NN];
static __device__ int   g_off[NN + 1];
static __device__ int   g_csr[EE];
static __device__ float g_nrm[EE];
static __device__ float g_dis[NN];

__device__ __forceinline__ uint32_t sm_u32(const void* p) {
    uint32_t a;
    asm("{ .reg .u64 t; cvta.to.shared.u64 t, %1; cvt.u32.u64 %0, t; }"
        : "=r"(a) : "l"(p));
    return a;
}

// ---------------- CSR build --------------------------------------------------
__global__ void k_zero() {
    int i = blockIdx.x * blockDim.x + threadIdx.x;
    if (i < NN) { g_cnt[i] = 0; g_cursor[i] = 0; }
}
__global__ void k_hist(const int* __restrict__ ei) {
    int e = blockIdx.x * blockDim.x + threadIdx.x;
    if (e < EE) atomicAdd(&g_cnt[ei[EE + e]], 1);
}
__global__ void k_scan() {
    __shared__ int sh[1024];
    const int CH = (NN + 1023) / 1024;
    int t = threadIdx.x;
    int beg = t * CH, end = beg + CH; if (end > NN) end = NN;
    int s = 0;
    for (int i = beg; i < end; i++) s += g_cnt[i];
    sh[t] = s;
    __syncthreads();
    for (int off = 1; off < 1024; off <<= 1) {
        int v = (t >= off) ? sh[t - off] : 0;
        __syncthreads();
        sh[t] += v;
        __syncthreads();
    }
    int run = (t == 0) ? 0 : sh[t - 1];
    for (int i = beg; i < end; i++) { g_off[i] = run; run += g_cnt[i]; }
    if (t == 1023) g_off[NN] = sh[1023];
    for (int i = beg; i < end; i++) g_dis[i] = rsqrtf((float)(g_cnt[i] + 1));
}
// scatter + edge-norm precompute (dis ready after k_scan)
__global__ void k_scatter(const int* __restrict__ ei) {
    int e = blockIdx.x * blockDim.x + threadIdx.x;
    if (e < EE) {
        int s = ei[e], d = ei[EE + e];
        int p = atomicAdd(&g_cursor[d], 1);
        int pos = g_off[d] + p;
        g_csr[pos] = s;
        g_nrm[pos] = g_dis[s] * g_dis[d];
    }
}

// ---------------- input pad+split --------------------------------------------
__global__ void k_pad(const float* __restrict__ x) {
    int idx = blockIdx.x * blockDim.x + threadIdx.x;     // over NN*192
    if (idx >= NN * 192) return;
    int m = idx / 192, j = idx - m * 192;
    int c0 = j * 4;
    float v[4];
    #pragma unroll
    for (int i = 0; i < 4; i++) {
        int c = c0 + i;
        v[i] = (c < 767) ? x[(size_t)m * 767 + c] : 0.f;
    }
    __nv_bfloat162 h0, h1, l0, l1;
    h0.x = __float2bfloat16_rn(v[0]); h0.y = __float2bfloat16_rn(v[1]);
    h1.x = __float2bfloat16_rn(v[2]); h1.y = __float2bfloat16_rn(v[3]);
    l0.x = __float2bfloat16_rn(v[0] - __bfloat162float(h0.x));
    l0.y = __float2bfloat16_rn(v[1] - __bfloat162float(h0.y));
    l1.x = __float2bfloat16_rn(v[2] - __bfloat162float(h1.x));
    l1.y = __float2bfloat16_rn(v[3] - __bfloat162float(h1.y));
    size_t o = (size_t)m * 768 + c0;
    *(__nv_bfloat162*)(g_Ah + o)     = h0;
    *(__nv_bfloat162*)(g_Ah + o + 2) = h1;
    *(__nv_bfloat162*)(g_Al + o)     = l0;
    *(__nv_bfloat162*)(g_Al + o + 2) = l1;
}

// ---------------- weight transpose+pad+split ---------------------------------
__global__ void k_wT(const float* __restrict__ W, int K, int Nc, int KP) {
    int idx = blockIdx.x * blockDim.x + threadIdx.x;
    if (idx >= Nc * KP) return;
    int n = idx / KP, k = idx - n * KP;
    float v = (k < K) ? W[(size_t)k * Nc + n] : 0.f;
    __nv_bfloat16 h = __float2bfloat16_rn(v);
    g_Wh[idx] = h;
    g_Wl[idx] = __float2bfloat16_rn(v - __bfloat162float(h));
}

// ---------------- bf16x3 tensor-core GEMM, 3-stage cp.async, XOR swizzle -----
#define PIPE 3
#define TILE_B 8192                  // 128 * 64 bytes
#define STAGE_B (4 * TILE_B)         // 32768
#define SMEM_MM (PIPE * STAGE_B)     // 98304 -> 2 CTAs/SM

__device__ __forceinline__ void cp16(uint32_t d, const void* s, int n) {
    asm volatile("cp.async.cg.shared.global [%0], [%1], 16, %2;\n"
                 :: "r"(d), "l"(s), "r"(n));
}
__device__ __forceinline__ void mma_bf16(float* d, const uint32_t* a, const uint32_t* b) {
    asm volatile(
        "mma.sync.aligned.m16n8k16.row.col.f32.bf16.bf16.f32 "
        "{%0,%1,%2,%3}, {%4,%5,%6,%7}, {%8,%9}, {%0,%1,%2,%3};"
        : "+f"(d[0]), "+f"(d[1]), "+f"(d[2]), "+f"(d[3])
        : "r"(a[0]), "r"(a[1]), "r"(a[2]), "r"(a[3]), "r"(b[0]), "r"(b[1]));
}
__device__ __forceinline__ void ldm_x4(uint32_t* r, uint32_t a) {
    asm volatile("ldmatrix.sync.aligned.m8n8.x4.shared.b16 {%0,%1,%2,%3}, [%4];"
                 : "=r"(r[0]), "=r"(r[1]), "=r"(r[2]), "=r"(r[3]) : "r"(a));
}
__device__ __forceinline__ void ldm_x2(uint32_t* r, uint32_t a) {
    asm volatile("ldmatrix.sync.aligned.m8n8.x2.shared.b16 {%0,%1}, [%2];"
                 : "=r"(r[0]), "=r"(r[1]) : "r"(a));
}
__device__ __forceinline__ uint32_t swzo(int row, int chunk) {
    return (uint32_t)(row * 64 + ((chunk ^ ((row >> 1) & 3)) * 16));
}

__global__ __launch_bounds__(256, 2) void k_mm(
    const __nv_bfloat16* __restrict__ Ah, const __nv_bfloat16* __restrict__ Al,
    float* __restrict__ C, int M, int KP, int Nc)
{
    extern __shared__ __nv_bfloat16 smem[];
    uint32_t sb = sm_u32(smem);
    int tid = threadIdx.x, lane = tid & 31, wid = tid >> 5;
    int wm = wid >> 2, wn = wid & 3;
    int m0 = blockIdx.y * 128, n0 = blockIdx.x * 128;
    const int NC = KP >> 5;
    int lr = lane >> 2, lc = (lane & 3) * 2;

    // ldmatrix per-lane swizzled offsets within a tile, per k-half
    int rbA = wm * 64 + (lane & 15);
    int csA = lane >> 4;
    uint32_t offA0 = swzo(rbA, csA);
    uint32_t offA1 = swzo(rbA, 2 + csA);
    int rbB = wn * 32 + (lane & 7);
    int csB = (lane >> 3) & 1;
    uint32_t offB0 = swzo(rbB, csB);
    uint32_t offB1 = swzo(rbB, 2 + csB);

    // cp.async coords
    int row = tid >> 1;
    int q0 = (tid & 1) * 2;
    int gm = m0 + row;
    int aok = (gm < M) ? 16 : 0;
    int gmc = (gm < M) ? gm : (M - 1);
    const __nv_bfloat16* pAh = Ah + (size_t)gmc * KP + q0 * 8;
    const __nv_bfloat16* pAl = Al + (size_t)gmc * KP + q0 * 8;
    const __nv_bfloat16* pBh = g_Wh + (size_t)(n0 + row) * KP + q0 * 8;
    const __nv_bfloat16* pBl = g_Wl + (size_t)(n0 + row) * KP + q0 * 8;
    uint32_t dro0 = swzo(row, q0);
    uint32_t dro1 = swzo(row, q0 + 1);

    auto issue = [&](int c) {
        int k0 = c << 5;
        uint32_t st = sb + (uint32_t)(c % PIPE) * STAGE_B;
        cp16(st + dro0,              pAh + k0,     aok);
        cp16(st + dro1,              pAh + k0 + 8, aok);
        cp16(st + TILE_B + dro0,     pAl + k0,     aok);
        cp16(st + TILE_B + dro1,     pAl + k0 + 8, aok);
        cp16(st + 2*TILE_B + dro0,   pBh + k0,     16);
        cp16(st + 2*TILE_B + dro1,   pBh + k0 + 8, 16);
        cp16(st + 3*TILE_B + dro0,   pBl + k0,     16);
        cp16(st + 3*TILE_B + dro1,   pBl + k0 + 8, 16);
    };

    float acc[4][4][4];
    #pragma unroll
    for (int i = 0; i < 4; i++)
        #pragma unroll
        for (int j = 0; j < 4; j++)
            #pragma unroll
            for (int r = 0; r < 4; r++) acc[i][j][r] = 0.f;

    issue(0);
    asm volatile("cp.async.commit_group;");
    issue(1);
    asm volatile("cp.async.commit_group;");

    for (int c = 0; c < NC; c++) {
        asm volatile("cp.async.wait_group 1;");
        __syncthreads();
        if (c + 2 < NC) issue(c + 2);
        asm volatile("cp.async.commit_group;");

        uint32_t stb = sb + (uint32_t)(c % PIPE) * STAGE_B;

        #pragma unroll
        for (int kh = 0; kh < 2; kh++) {
            uint32_t oA = kh ? offA1 : offA0;
            uint32_t oB = kh ? offB1 : offB0;
            // B fragments first (8 LDSM)
            uint32_t bh[4][2], bl[4][2];
            #pragma unroll
            for (int nf = 0; nf < 4; nf++) {
                uint32_t no = (uint32_t)nf * 512;
                ldm_x2(bh[nf], stb + 2*TILE_B + oB + no);
                ldm_x2(bl[nf], stb + 3*TILE_B + oB + no);
            }
            // A fragments streamed per mf, MMAs immediately after
            #pragma unroll
            for (int mf = 0; mf < 4; mf++) {
                uint32_t mo = (uint32_t)mf * 1024;
                uint32_t ah[4], al[4];
                ldm_x4(ah, stb + oA + mo);
                ldm_x4(al, stb + TILE_B + oA + mo);
                #pragma unroll
                for (int nf = 0; nf < 4; nf++) {
                    mma_bf16(acc[mf][nf], ah, bh[nf]);
                    mma_bf16(acc[mf][nf], ah, bl[nf]);
                    mma_bf16(acc[mf][nf], al, bh[nf]);
                }
            }
        }
    }

    #pragma unroll
    for (int mf = 0; mf < 4; mf++) {
        int r0 = m0 + wm * 64 + mf * 16 + lr;
        #pragma unroll
        for (int nf = 0; nf < 4; nf++) {
            int cc = n0 + wn * 32 + nf * 8 + lc;
            if (r0 < M)
                *(float2*)(C + (size_t)r0 * Nc + cc) =
                    make_float2(acc[mf][nf][0], acc[mf][nf][1]);
            if (r0 + 8 < M)
                *(float2*)(C + (size_t)(r0 + 8) * Nc + cc) =
                    make_float2(acc[mf][nf][2], acc[mf][nf][3]);
        }
    }
}

// ---------------- small GEMM for layer 6: K=128, N=10 ------------------------
__global__ __launch_bounds__(256) void k_small(
    const __nv_bfloat16* __restrict__ Ah, const __nv_bfloat16* __restrict__ Al,
    const float* __restrict__ W, float* __restrict__ C)
{
    __shared__ float Ws[128 * 10];
    for (int i = threadIdx.x; i < 1280; i += 256) Ws[i] = W[i];
    __syncthreads();
    int idx = blockIdx.x * 256 + threadIdx.x;
    if (idx >= NN * 10) return;
    int m = idx / 10, n = idx - m * 10;
    const __nv_bfloat16* ah = Ah + (size_t)m * 128;
    const __nv_bfloat16* al = Al + (size_t)m * 128;
    float acc = 0.f;
    #pragma unroll 8
    for (int k = 0; k < 128; k++) {
        float a = __bfloat162float(ah[k]) + __bfloat162float(al[k]);
        acc = fmaf(a, Ws[k * 10 + n], acc);
    }
    C[idx] = acc;
}

// ---------------- aggregation -> bf16 hi/lo (unroll 4, precomputed norms) ----
__global__ void k_aggv(const float4* __restrict__ h, const float4* __restrict__ bias,
                       __nv_bfloat162* __restrict__ oh, __nv_bfloat162* __restrict__ ol,
                       int relu)
{
    int node = blockIdx.x;
    int t = threadIdx.x;
    int F4 = blockDim.x;
    float dd = g_dis[node];
    float w0 = dd * dd;
    float4 a = h[(size_t)node * F4 + t];
    float4 acc = make_float4(a.x * w0, a.y * w0, a.z * w0, a.w * w0);
    int e = g_off[node], end = g_off[node + 1];
    for (; e + 3 < end; e += 4) {
        int s0 = g_csr[e], s1 = g_csr[e+1], s2 = g_csr[e+2], s3 = g_csr[e+3];
        float u0 = g_nrm[e], u1 = g_nrm[e+1], u2 = g_nrm[e+2], u3 = g_nrm[e+3];
        float4 v0 = h[(size_t)s0 * F4 + t];
        float4 v1 = h[(size_t)s1 * F4 + t];
        float4 v2 = h[(size_t)s2 * F4 + t];
        float4 v3 = h[(size_t)s3 * F4 + t];
        acc.x = fmaf(v0.x, u0, fmaf(v1.x, u1, fmaf(v2.x, u2, fmaf(v3.x, u3, acc.x))));
        acc.y = fmaf(v0.y, u0, fmaf(v1.y, u1, fmaf(v2.y, u2, fmaf(v3.y, u3, acc.y))));
        acc.z = fmaf(v0.z, u0, fmaf(v1.z, u1, fmaf(v2.z, u2, fmaf(v3.z, u3, acc.z))));
        acc.w = fmaf(v0.w, u0, fmaf(v1.w, u1, fmaf(v2.w, u2, fmaf(v3.w, u3, acc.w))));
    }
    for (; e < end; e++) {
        int s0 = g_csr[e];
        float u0 = g_nrm[e];
        float4 v0 = h[(size_t)s0 * F4 + t];
        acc.x = fmaf(v0.x, u0, acc.x);
        acc.y = fmaf(v0.y, u0, acc.y);
        acc.z = fmaf(v0.z, u0, acc.z);
        acc.w = fmaf(v0.w, u0, acc.w);
    }
    float4 bb = bias[t];
    float4 r = make_float4(acc.x + bb.x, acc.y + bb.y, acc.z + bb.z, acc.w + bb.w);
    if (relu) {
        r.x = fmaxf(r.x, 0.f); r.y = fmaxf(r.y, 0.f);
        r.z = fmaxf(r.z, 0.f); r.w = fmaxf(r.w, 0.f);
    }
    __nv_bfloat162 h0, h1, l0, l1;
    h0.x = __float2bfloat16_rn(r.x); h0.y = __float2bfloat16_rn(r.y);
    h1.x = __float2bfloat16_rn(r.z); h1.y = __float2bfloat16_rn(r.w);
    l0.x = __float2bfloat16_rn(r.x - __bfloat162float(h0.x));
    l0.y = __float2bfloat16_rn(r.y - __bfloat162float(h0.y));
    l1.x = __float2bfloat16_rn(r.z - __bfloat162float(h1.x));
    l1.y = __float2bfloat16_rn(r.w - __bfloat162float(h1.y));
    size_t o = ((size_t)node * F4 + t) * 2;
    oh[o] = h0; oh[o + 1] = h1;
    ol[o] = l0; ol[o + 1] = l1;
}

__global__ void k_agg10(const float* __restrict__ h, const float* __restrict__ bias,
                        float* __restrict__ out)
{
    int node = blockIdx.x;
    int f = threadIdx.x;
    if (f >= 10) return;
    float dd = g_dis[node];
    float acc = h[(size_t)node * 10 + f] * dd * dd;
    int e = g_off[node], end = g_off[node + 1];
    for (; e < end; e++) {
        int s = g_csr[e];
        acc = fmaf(h[(size_t)s * 10 + f], g_nrm[e], acc);
    }
    out[(size_t)node * 10 + f] = acc + bias[f];
}

// ---------------- log_softmax over dim=10 ------------------------------------
__global__ void k_lsm(const float* __restrict__ in, float* __restrict__ out) {
    int i = blockIdx.x * blockDim.x + threadIdx.x;
    if (i >= NN) return;
    const float* r = in + (size_t)i * 10;
    float m = -1e30f;
    #pragma unroll
    for (int j = 0; j < 10; j++) m = fmaxf(m, r[j]);
    float s = 0.f;
    #pragma unroll
    for (int j = 0; j < 10; j++) s += __expf(r[j] - m);
    float l = __logf(s);
    float* o = out + (size_t)i * 10;
    #pragma unroll
    for (int j = 0; j < 10; j++) o[j] = r[j] - m - l;
}

// ---------------- driver -----------------------------------------------------
extern "C" void kernel_launch(void* const* d_in, const int* in_sizes, int n_in,
                              void* d_out, int out_size)
{
    const float* x  = (const float*)d_in[0];
    const int*   ei = (const int*)d_in[1];
    const float* W[6]; const float* b[6];
    for (int i = 0; i < 6; i++) {
        W[i] = (const float*)d_in[2 + 2 * i];
        b[i] = (const float*)d_in[3 + 2 * i];
    }

    __nv_bfloat16 *Ah, *Al;
    float *C, *S, *T;
    cudaGetSymbolAddress((void**)&Ah, g_Ah);
    cudaGetSymbolAddress((void**)&Al, g_Al);
    cudaGetSymbolAddress((void**)&C,  g_C);
    cudaGetSymbolAddress((void**)&S,  g_S);
    cudaGetSymbolAddress((void**)&T,  g_T);

    cudaFuncSetAttribute(k_mm, cudaFuncAttributeMaxDynamicSharedMemorySize, SMEM_MM);

    const int dims[7] = {767, 640, 512, 384, 256, 128, 10};
    const int KPs[6]  = {768, 640, 512, 384, 256, 128};

    // order chosen so k_mm (layer 1) is the 4th launch for ncu capture
    k_pad <<<(NN * 192 + 255) / 256, 256>>>(x);                          // 1
    k_wT  <<<(640 * 768 + 255) / 256, 256>>>(W[0], 767, 640, 768);      // 2
    k_zero<<<(NN + 255) / 256, 256>>>();                                 // 3
    {
        dim3 grid(640 / 128, (NN + 127) / 128);
        k_mm<<<grid, 256, SMEM_MM>>>(Ah, Al, C, NN, 768, 640);           // 4
    }
    k_hist   <<<(EE + 255) / 256, 256>>>(ei);                            // 5
    k_scan   <<<1, 1024>>>();                                            // 6
    k_scatter<<<(EE + 255) / 256, 256>>>(ei);                            // 7
    k_aggv<<<NN, 640 / 4>>>((const float4*)C, (const float4*)b[0],
                            (__nv_bfloat162*)Ah, (__nv_bfloat162*)Al, 1);// 8

    for (int l = 1; l < 5; l++) {
        int K = dims[l], F = dims[l + 1], KP = KPs[l];
        k_wT<<<(F * KP + 255) / 256, 256>>>(W[l], K, F, KP);
        dim3 grid(F / 128, (NN + 127) / 128);
        k_mm<<<grid, 256, SMEM_MM>>>(Ah, Al, C, NN, KP, F);
        k_aggv<<<NN, F / 4>>>((const float4*)C, (const float4*)b[l],
                              (__nv_bfloat162*)Ah, (__nv_bfloat162*)Al, 1);
    }
    // layer 6: K=128 -> N=10, fp32
    k_small<<<(NN * 10 + 255) / 256, 256>>>(Ah, Al, W[5], S);
    k_agg10<<<NN, 32>>>(S, b[5], T);
    k_lsm<<<(NN + 255) / 256, 256>>>(T, (float*)d_out);
}

// round 9
// speedup vs baseline: 2.7586x; 1.0603x over previous
#include <cuda_runtime.h>
#include <cuda_bf16.h>
#include <cstdint>
#include <math.h>

#define NN 50000
#define EE 800000

// ---------------- scratch (static device globals) ---------------------------
static __device__ __align__(16) __nv_bfloat16 g_Ah[(size_t)NN * 768];
static __device__ __align__(16) __nv_bfloat16 g_Al[(size_t)NN * 768];
static __device__ __align__(16) float         g_C[(size_t)NN * 640];
#define WTOT 1146880
static __device__ __align__(16) __nv_bfloat16 g_Wh[WTOT];
static __device__ __align__(16) __nv_bfloat16 g_Wl[WTOT];
static __device__ float g_S[(size_t)NN * 10];
static __device__ int   g_cnt[NN];
static __device__ int   g_cursor[NN];
static __device__ int   g_off[NN + 1];
static __device__ int   g_csr[EE];
static __device__ float g_nrm[EE];
static __device__ float g_dis[NN];

__device__ __forceinline__ uint32_t sm_u32(const void* p) {
    uint32_t a;
    asm("{ .reg .u64 t; cvta.to.shared.u64 t, %1; cvt.u32.u64 %0, t; }"
        : "=r"(a) : "l"(p));
    return a;
}

// ---------------- streams/events (created pre-main, outside capture) ---------
struct HxStreams {
    cudaStream_t s1, s2;
    cudaEvent_t eFork, eCsr, eWT;
    HxStreams() {
        cudaStreamCreateWithFlags(&s1, cudaStreamNonBlocking);
        cudaStreamCreateWithFlags(&s2, cudaStreamNonBlocking);
        cudaEventCreateWithFlags(&eFork, cudaEventDisableTiming);
        cudaEventCreateWithFlags(&eCsr,  cudaEventDisableTiming);
        cudaEventCreateWithFlags(&eWT,   cudaEventDisableTiming);
    }
};
static HxStreams hx;

// ---------------- CSR build --------------------------------------------------
__global__ void k_zero() {
    int i = blockIdx.x * blockDim.x + threadIdx.x;
    if (i < NN) { g_cnt[i] = 0; g_cursor[i] = 0; }
}
__global__ void k_hist(const int* __restrict__ ei) {
    int e = blockIdx.x * blockDim.x + threadIdx.x;
    if (e < EE) atomicAdd(&g_cnt[ei[EE + e]], 1);
}
__global__ void k_scan() {
    __shared__ int sh[1024];
    const int CH = (NN + 1023) / 1024;
    int t = threadIdx.x;
    int beg = t * CH, end = beg + CH; if (end > NN) end = NN;
    int s = 0;
    for (int i = beg; i < end; i++) s += g_cnt[i];
    sh[t] = s;
    __syncthreads();
    for (int off = 1; off < 1024; off <<= 1) {
        int v = (t >= off) ? sh[t - off] : 0;
        __syncthreads();
        sh[t] += v;
        __syncthreads();
    }
    int run = (t == 0) ? 0 : sh[t - 1];
    for (int i = beg; i < end; i++) { g_off[i] = run; run += g_cnt[i]; }
    if (t == 1023) g_off[NN] = sh[1023];
    for (int i = beg; i < end; i++) g_dis[i] = rsqrtf((float)(g_cnt[i] + 1));
}
__global__ void k_scatter(const int* __restrict__ ei) {
    int e = blockIdx.x * blockDim.x + threadIdx.x;
    if (e < EE) {
        int s = ei[e], d = ei[EE + e];
        int p = atomicAdd(&g_cursor[d], 1);
        int pos = g_off[d] + p;
        g_csr[pos] = s;
        g_nrm[pos] = g_dis[s] * g_dis[d];
    }
}

// ---------------- input pad+split --------------------------------------------
__global__ void k_pad(const float* __restrict__ x) {
    int idx = blockIdx.x * blockDim.x + threadIdx.x;
    if (idx >= NN * 192) return;
    int m = idx / 192, j = idx - m * 192;
    int c0 = j * 4;
    float v[4];
    #pragma unroll
    for (int i = 0; i < 4; i++) {
        int c = c0 + i;
        v[i] = (c < 767) ? x[(size_t)m * 767 + c] : 0.f;
    }
    __nv_bfloat162 h0, h1, l0, l1;
    h0.x = __float2bfloat16_rn(v[0]); h0.y = __float2bfloat16_rn(v[1]);
    h1.x = __float2bfloat16_rn(v[2]); h1.y = __float2bfloat16_rn(v[3]);
    l0.x = __float2bfloat16_rn(v[0] - __bfloat162float(h0.x));
    l0.y = __float2bfloat16_rn(v[1] - __bfloat162float(h0.y));
    l1.x = __float2bfloat16_rn(v[2] - __bfloat162float(h1.x));
    l1.y = __float2bfloat16_rn(v[3] - __bfloat162float(h1.y));
    size_t o = (size_t)m * 768 + c0;
    *(__nv_bfloat162*)(g_Ah + o)     = h0;
    *(__nv_bfloat162*)(g_Ah + o + 2) = h1;
    *(__nv_bfloat162*)(g_Al + o)     = l0;
    *(__nv_bfloat162*)(g_Al + o + 2) = l1;
}

// ---------------- all-layer weight transpose+pad+split -----------------------
struct WPtrs { const float* p[5]; };
// layer geometry: K (true), Nc, KP, elem-offset
__constant__ const int c_K[5]  = {767, 640, 512, 384, 256};
__constant__ const int c_Nc[5] = {640, 512, 384, 256, 128};
__constant__ const int c_KP[5] = {768, 640, 512, 384, 256};
__constant__ const int c_WO[6] = {0, 491520, 819200, 1015808, 1114112, 1146880};

__global__ void k_wT_all(WPtrs wp) {
    int idx = blockIdx.x * blockDim.x + threadIdx.x;
    if (idx >= WTOT) return;
    int l = 0;
    if (idx >= c_WO[1]) l = 1;
    if (idx >= c_WO[2]) l = 2;
    if (idx >= c_WO[3]) l = 3;
    if (idx >= c_WO[4]) l = 4;
    int local = idx - c_WO[l];
    int KP = c_KP[l], Nc = c_Nc[l], K = c_K[l];
    int n = local / KP, k = local - n * KP;
    float v = (k < K) ? wp.p[l][(size_t)k * Nc + n] : 0.f;
    __nv_bfloat16 h = __float2bfloat16_rn(v);
    g_Wh[idx] = h;
    g_Wl[idx] = __float2bfloat16_rn(v - __bfloat162float(h));
}

// ---------------- bf16x3 tensor-core GEMM ------------------------------------
#define PIPE 3
#define TILE_B 8192
#define STAGE_B (4 * TILE_B)
#define SMEM_MM (PIPE * STAGE_B)

__device__ __forceinline__ void cp16(uint32_t d, const void* s, int n) {
    asm volatile("cp.async.cg.shared.global [%0], [%1], 16, %2;\n"
                 :: "r"(d), "l"(s), "r"(n));
}
__device__ __forceinline__ void mma_bf16(float* d, const uint32_t* a, const uint32_t* b) {
    asm volatile(
        "mma.sync.aligned.m16n8k16.row.col.f32.bf16.bf16.f32 "
        "{%0,%1,%2,%3}, {%4,%5,%6,%7}, {%8,%9}, {%0,%1,%2,%3};"
        : "+f"(d[0]), "+f"(d[1]), "+f"(d[2]), "+f"(d[3])
        : "r"(a[0]), "r"(a[1]), "r"(a[2]), "r"(a[3]), "r"(b[0]), "r"(b[1]));
}
__device__ __forceinline__ void ldm_x4(uint32_t* r, uint32_t a) {
    asm volatile("ldmatrix.sync.aligned.m8n8.x4.shared.b16 {%0,%1,%2,%3}, [%4];"
                 : "=r"(r[0]), "=r"(r[1]), "=r"(r[2]), "=r"(r[3]) : "r"(a));
}
__device__ __forceinline__ uint32_t swzo(int row, int chunk) {
    return (uint32_t)(row * 64 + ((chunk ^ ((row >> 1) & 3)) * 16));
}

__global__ __launch_bounds__(256, 2) void k_mm(
    const __nv_bfloat16* __restrict__ Ah, const __nv_bfloat16* __restrict__ Al,
    const __nv_bfloat16* __restrict__ Wh, const __nv_bfloat16* __restrict__ Wl,
    float* __restrict__ C, int M, int KP, int Nc)
{
    extern __shared__ __nv_bfloat16 smem[];
    uint32_t sb = sm_u32(smem);
    int tid = threadIdx.x, lane = tid & 31, wid = tid >> 5;
    int wm = wid >> 2, wn = wid & 3;
    int m0 = blockIdx.y * 128, n0 = blockIdx.x * 128;
    const int NC = KP >> 5;
    int lr = lane >> 2, lc = (lane & 3) * 2;

    // A ldmatrix offsets (x4: 16 rows x 2 chunks)
    int rbA = wm * 64 + (lane & 15);
    int csA = lane >> 4;
    uint32_t offA0 = swzo(rbA, csA);
    uint32_t offA1 = swzo(rbA, 2 + csA);
    // B ldmatrix offsets (x4 pairs: rows nfp*16 + lane-mapped 16 rows x 2 chunks)
    int rbB = wn * 32 + (lane & 7) + ((lane >> 4) & 1) * 8;
    int csB = (lane >> 3) & 1;
    uint32_t offB[2][2];
    #pragma unroll
    for (int kh = 0; kh < 2; kh++)
        #pragma unroll
        for (int nfp = 0; nfp < 2; nfp++)
            offB[kh][nfp] = swzo(rbB + nfp * 16, csB + kh * 2);

    // cp.async coords
    int row = tid >> 1;
    int q0 = (tid & 1) * 2;
    int gm = m0 + row;
    int aok = (gm < M) ? 16 : 0;
    int gmc = (gm < M) ? gm : (M - 1);
    const __nv_bfloat16* pAh = Ah + (size_t)gmc * KP + q0 * 8;
    const __nv_bfloat16* pAl = Al + (size_t)gmc * KP + q0 * 8;
    const __nv_bfloat16* pBh = Wh + (size_t)(n0 + row) * KP + q0 * 8;
    const __nv_bfloat16* pBl = Wl + (size_t)(n0 + row) * KP + q0 * 8;
    uint32_t dro0 = swzo(row, q0);
    uint32_t dro1 = swzo(row, q0 + 1);

    auto issue = [&](int c) {
        int k0 = c << 5;
        uint32_t st = sb + (uint32_t)(c % PIPE) * STAGE_B;
        cp16(st + dro0,              pAh + k0,     aok);
        cp16(st + dro1,              pAh + k0 + 8, aok);
        cp16(st + TILE_B + dro0,     pAl + k0,     aok);
        cp16(st + TILE_B + dro1,     pAl + k0 + 8, aok);
        cp16(st + 2*TILE_B + dro0,   pBh + k0,     16);
        cp16(st + 2*TILE_B + dro1,   pBh + k0 + 8, 16);
        cp16(st + 3*TILE_B + dro0,   pBl + k0,     16);
        cp16(st + 3*TILE_B + dro1,   pBl + k0 + 8, 16);
    };

    float acc[4][4][4];
    #pragma unroll
    for (int i = 0; i < 4; i++)
        #pragma unroll
        for (int j = 0; j < 4; j++)
            #pragma unroll
            for (int r = 0; r < 4; r++) acc[i][j][r] = 0.f;

    issue(0);
    asm volatile("cp.async.commit_group;");
    issue(1);
    asm volatile("cp.async.commit_group;");

    for (int c = 0; c < NC; c++) {
        asm volatile("cp.async.wait_group 1;");
        __syncthreads();
        if (c + 2 < NC) issue(c + 2);
        asm volatile("cp.async.commit_group;");

        uint32_t stb = sb + (uint32_t)(c % PIPE) * STAGE_B;

        #pragma unroll
        for (int kh = 0; kh < 2; kh++) {
            uint32_t oA = kh ? offA1 : offA0;
            uint32_t bh[4][2], bl[4][2];
            #pragma unroll
            for (int nfp = 0; nfp < 2; nfp++) {
                uint32_t t[4];
                ldm_x4(t, stb + 2*TILE_B + offB[kh][nfp]);
                bh[2*nfp][0] = t[0]; bh[2*nfp][1] = t[1];
                bh[2*nfp+1][0] = t[2]; bh[2*nfp+1][1] = t[3];
                ldm_x4(t, stb + 3*TILE_B + offB[kh][nfp]);
                bl[2*nfp][0] = t[0]; bl[2*nfp][1] = t[1];
                bl[2*nfp+1][0] = t[2]; bl[2*nfp+1][1] = t[3];
            }
            #pragma unroll
            for (int mf = 0; mf < 4; mf++) {
                uint32_t mo = (uint32_t)mf * 1024;
                uint32_t ah[4], al[4];
                ldm_x4(ah, stb + oA + mo);
                ldm_x4(al, stb + TILE_B + oA + mo);
                #pragma unroll
                for (int nf = 0; nf < 4; nf++) {
                    mma_bf16(acc[mf][nf], ah, bh[nf]);
                    mma_bf16(acc[mf][nf], ah, bl[nf]);
                    mma_bf16(acc[mf][nf], al, bh[nf]);
                }
            }
        }
    }

    #pragma unroll
    for (int mf = 0; mf < 4; mf++) {
        int r0 = m0 + wm * 64 + mf * 16 + lr;
        #pragma unroll
        for (int nf = 0; nf < 4; nf++) {
            int cc = n0 + wn * 32 + nf * 8 + lc;
            if (r0 < M)
                *(float2*)(C + (size_t)r0 * Nc + cc) =
                    make_float2(acc[mf][nf][0], acc[mf][nf][1]);
            if (r0 + 8 < M)
                *(float2*)(C + (size_t)(r0 + 8) * Nc + cc) =
                    make_float2(acc[mf][nf][2], acc[mf][nf][3]);
        }
    }
}

// ---------------- small GEMM for layer 6: K=128, N=10 ------------------------
__global__ __launch_bounds__(256) void k_small(
    const __nv_bfloat16* __restrict__ Ah, const __nv_bfloat16* __restrict__ Al,
    const float* __restrict__ W, float* __restrict__ C)
{
    __shared__ float Ws[128 * 10];
    for (int i = threadIdx.x; i < 1280; i += 256) Ws[i] = W[i];
    __syncthreads();
    int idx = blockIdx.x * 256 + threadIdx.x;
    if (idx >= NN * 10) return;
    int m = idx / 10, n = idx - m * 10;
    const __nv_bfloat16* ah = Ah + (size_t)m * 128;
    const __nv_bfloat16* al = Al + (size_t)m * 128;
    float acc = 0.f;
    #pragma unroll 8
    for (int k = 0; k < 128; k++) {
        float a = __bfloat162float(ah[k]) + __bfloat162float(al[k]);
        acc = fmaf(a, Ws[k * 10 + n], acc);
    }
    C[idx] = acc;
}

// ---------------- aggregation -> bf16 hi/lo ----------------------------------
__global__ void k_aggv(const float4* __restrict__ h, const float4* __restrict__ bias,
                       __nv_bfloat162* __restrict__ oh, __nv_bfloat162* __restrict__ ol,
                       int relu)
{
    int node = blockIdx.x;
    int t = threadIdx.x;
    int F4 = blockDim.x;
    float dd = g_dis[node];
    float w0 = dd * dd;
    float4 a = h[(size_t)node * F4 + t];
    float4 acc = make_float4(a.x * w0, a.y * w0, a.z * w0, a.w * w0);
    int e = g_off[node], end = g_off[node + 1];
    for (; e + 3 < end; e += 4) {
        int s0 = g_csr[e], s1 = g_csr[e+1], s2 = g_csr[e+2], s3 = g_csr[e+3];
        float u0 = g_nrm[e], u1 = g_nrm[e+1], u2 = g_nrm[e+2], u3 = g_nrm[e+3];
        float4 v0 = h[(size_t)s0 * F4 + t];
        float4 v1 = h[(size_t)s1 * F4 + t];
        float4 v2 = h[(size_t)s2 * F4 + t];
        float4 v3 = h[(size_t)s3 * F4 + t];
        acc.x = fmaf(v0.x, u0, fmaf(v1.x, u1, fmaf(v2.x, u2, fmaf(v3.x, u3, acc.x))));
        acc.y = fmaf(v0.y, u0, fmaf(v1.y, u1, fmaf(v2.y, u2, fmaf(v3.y, u3, acc.y))));
        acc.z = fmaf(v0.z, u0, fmaf(v1.z, u1, fmaf(v2.z, u2, fmaf(v3.z, u3, acc.z))));
        acc.w = fmaf(v0.w, u0, fmaf(v1.w, u1, fmaf(v2.w, u2, fmaf(v3.w, u3, acc.w))));
    }
    for (; e < end; e++) {
        int s0 = g_csr[e];
        float u0 = g_nrm[e];
        float4 v0 = h[(size_t)s0 * F4 + t];
        acc.x = fmaf(v0.x, u0, acc.x);
        acc.y = fmaf(v0.y, u0, acc.y);
        acc.z = fmaf(v0.z, u0, acc.z);
        acc.w = fmaf(v0.w, u0, acc.w);
    }
    float4 bb = bias[t];
    float4 r = make_float4(acc.x + bb.x, acc.y + bb.y, acc.z + bb.z, acc.w + bb.w);
    if (relu) {
        r.x = fmaxf(r.x, 0.f); r.y = fmaxf(r.y, 0.f);
        r.z = fmaxf(r.z, 0.f); r.w = fmaxf(r.w, 0.f);
    }
    __nv_bfloat162 h0, h1, l0, l1;
    h0.x = __float2bfloat16_rn(r.x); h0.y = __float2bfloat16_rn(r.y);
    h1.x = __float2bfloat16_rn(r.z); h1.y = __float2bfloat16_rn(r.w);
    l0.x = __float2bfloat16_rn(r.x - __bfloat162float(h0.x));
    l0.y = __float2bfloat16_rn(r.y - __bfloat162float(h0.y));
    l1.x = __float2bfloat16_rn(r.z - __bfloat162float(h1.x));
    l1.y = __float2bfloat16_rn(r.w - __bfloat162float(h1.y));
    size_t o = ((size_t)node * F4 + t) * 2;
    oh[o] = h0; oh[o + 1] = h1;
    ol[o] = l0; ol[o + 1] = l1;
}

// ---------------- fused final agg + log_softmax ------------------------------
__global__ void k_tail(const float* __restrict__ S, const float* __restrict__ bias,
                       float* __restrict__ out)
{
    int node = blockIdx.x;
    int f = threadIdx.x;            // 32 threads, 10 active
    bool act = f < 10;
    float dd = g_dis[node];
    float val = 0.f;
    if (act) {
        val = S[(size_t)node * 10 + f] * dd * dd;
        int e = g_off[node], end = g_off[node + 1];
        for (; e < end; e++) {
            int s = g_csr[e];
            val = fmaf(S[(size_t)s * 10 + f], g_nrm[e], val);
        }
        val += bias[f];
    }
    float m = act ? val : -1e30f;
    #pragma unroll
    for (int o = 16; o; o >>= 1) m = fmaxf(m, __shfl_xor_sync(0xFFFFFFFFu, m, o));
    float ex = act ? __expf(val - m) : 0.f;
    #pragma unroll
    for (int o = 16; o; o >>= 1) ex += __shfl_xor_sync(0xFFFFFFFFu, ex, o);
    if (act) out[(size_t)node * 10 + f] = val - m - __logf(ex);
}

// ---------------- driver -----------------------------------------------------
extern "C" void kernel_launch(void* const* d_in, const int* in_sizes, int n_in,
                              void* d_out, int out_size)
{
    const float* x  = (const float*)d_in[0];
    const int*   ei = (const int*)d_in[1];
    const float* W[6]; const float* b[6];
    for (int i = 0; i < 6; i++) {
        W[i] = (const float*)d_in[2 + 2 * i];
        b[i] = (const float*)d_in[3 + 2 * i];
    }

    __nv_bfloat16 *Ah, *Al, *Wh, *Wl;
    float *C, *S;
    cudaGetSymbolAddress((void**)&Ah, g_Ah);
    cudaGetSymbolAddress((void**)&Al, g_Al);
    cudaGetSymbolAddress((void**)&Wh, g_Wh);
    cudaGetSymbolAddress((void**)&Wl, g_Wl);
    cudaGetSymbolAddress((void**)&C,  g_C);
    cudaGetSymbolAddress((void**)&S,  g_S);

    cudaFuncSetAttribute(k_mm, cudaFuncAttributeMaxDynamicSharedMemorySize, SMEM_MM);

    const int dims[7] = {767, 640, 512, 384, 256, 128, 10};
    const int KPs[6]  = {768, 640, 512, 384, 256, 128};
    const int WO[5]   = {0, 491520, 819200, 1015808, 1114112};

    // fork point
    cudaEventRecord(hx.eFork, 0);

    // launch #1: pad (main stream)
    k_pad<<<(NN * 192 + 255) / 256, 256>>>(x);

    // launch #2: weights (s2)
    cudaStreamWaitEvent(hx.s2, hx.eFork, 0);
    WPtrs wp; for (int i = 0; i < 5; i++) wp.p[i] = W[i];
    k_wT_all<<<(WTOT + 255) / 256, 256, 0, hx.s2>>>(wp);
    cudaEventRecord(hx.eWT, hx.s2);

    // launch #3: CSR zero (s1)
    cudaStreamWaitEvent(hx.s1, hx.eFork, 0);
    k_zero<<<(NN + 255) / 256, 256, 0, hx.s1>>>();

    // launch #4: layer-1 GEMM (main, after pad + weights)
    cudaStreamWaitEvent(0, hx.eWT, 0);
    {
        dim3 grid(640 / 128, (NN + 127) / 128);
        k_mm<<<grid, 256, SMEM_MM>>>(Ah, Al, Wh + WO[0], Wl + WO[0], C, NN, 768, 640);
    }

    // rest of CSR chain (s1) — overlaps with layer-1 GEMM
    k_hist   <<<(EE + 255) / 256, 256, 0, hx.s1>>>(ei);
    k_scan   <<<1, 1024, 0, hx.s1>>>();
    k_scatter<<<(EE + 255) / 256, 256, 0, hx.s1>>>(ei);
    cudaEventRecord(hx.eCsr, hx.s1);

    // aggregation layer 1 (needs CSR)
    cudaStreamWaitEvent(0, hx.eCsr, 0);
    k_aggv<<<NN, 640 / 4>>>((const float4*)C, (const float4*)b[0],
                            (__nv_bfloat162*)Ah, (__nv_bfloat162*)Al, 1);

    for (int l = 1; l < 5; l++) {
        int F = dims[l + 1], KP = KPs[l];
        dim3 grid(F / 128, (NN + 127) / 128);
        k_mm<<<grid, 256, SMEM_MM>>>(Ah, Al, Wh + WO[l], Wl + WO[l], C, NN, KP, F);
        k_aggv<<<NN, F / 4>>>((const float4*)C, (const float4*)b[l],
                              (__nv_bfloat162*)Ah, (__nv_bfloat162*)Al, 1);
    }
    // layer 6: K=128 -> N=10 fp32, then fused agg+log_softmax
    k_small<<<(NN * 10 + 255) / 256, 256>>>(Ah, Al, W[5], S);
    k_tail<<<NN, 32>>>(S, b[5], (float*)d_out);
}